// round 13
// baseline (speedup 1.0000x reference)
#include <cuda_runtime.h>
#include <math.h>

#define TT   128
#define BB   512
#define HH   128
#define EMBD 300
#define DD   256
#define G3   384
#define EPSF 1e-7f

typedef long long ll;

__device__ float g_xp_f[TT * BB * G3];
__device__ float g_xp_b[TT * BB * G3];
__device__ float g_ys_f[TT * BB * HH];
__device__ float g_ys_b[TT * BB * HH];
__device__ float g_hyp[TT * BB * DD];
__device__ float g_scores[TT * BB];
__device__ float g_rr2[TT * BB];
__device__ float g_cc[2];   // [cosh(rc), sinh(rc)/rc]

// ---- tf32 helpers ----
__device__ __forceinline__ unsigned f2tf32(float v) {      // RNA (used in K2 recurrence)
    unsigned u;
    asm("cvt.rna.tf32.f32 %0, %1;" : "=r"(u) : "f"(v));
    return u;
}
__device__ __forceinline__ void mma_tf32(float* c, const unsigned* a, const unsigned* b) {
    asm volatile(
        "mma.sync.aligned.m16n8k8.row.col.f32.tf32.tf32.f32 "
        "{%0,%1,%2,%3}, {%4,%5,%6,%7}, {%8,%9}, {%0,%1,%2,%3};"
        : "+f"(c[0]), "+f"(c[1]), "+f"(c[2]), "+f"(c[3])
        : "r"(a[0]), "r"(a[1]), "r"(a[2]), "r"(a[3]), "r"(b[0]), "r"(b[1]));
}

// ---- K1/K3 fragment-major layout ----
#define ACH 1032
#define BCH 1032
#define MMA_SMEM ((8 * ACH + 8 * BCH) * 4)   // 66,048 B

__device__ __forceinline__ int a_off(int r, int kk) {
    return (kk >> 3) * ACH + (r >> 4) * 128 + ((((r & 7) << 2) | (kk & 3)) << 2)
           + ((r >> 3) & 1) + (((kk >> 2) & 1) << 1);
}
__device__ __forceinline__ int b_off(int c, int kk) {
    return (kk >> 3) * BCH + (c >> 3) * 64 + ((((c & 7) << 2) | (kk & 3)) << 1)
           + ((kk >> 2) & 1);
}

// K2 smem: B-frags ktiles 6..15 (10 kt) + double-buffered h_A
// sB = 8 warps * 10 kt * 6 nt * 64 floats = 30720 floats = 122,880 B ; hA = 16,384 B
#define K2_SMEM (122880 + 16384)   // 139,264 B

// ============================================================
// K0: centroid constants — idempotent
// ============================================================
__global__ void k0_cent(const float* __restrict__ cent)
{
    const int lane = threadIdx.x;
    float c2 = 0.f;
    #pragma unroll
    for (int i = 0; i < 8; i++) {
        const float cv = cent[lane + 32 * i];
        c2 += cv * cv;
    }
    #pragma unroll
    for (int o = 16; o; o >>= 1) c2 += __shfl_xor_sync(0xffffffffu, c2, o);
    if (lane == 0) {
        const float rc = sqrtf(c2);
        g_cc[0] = coshf(rc);
        g_cc[1] = sinhf(rc) / rc;
    }
}

// ============================================================
// K1: embed gather + input projections via tf32 mma.
// RZ-truncated operands (raw fp32 bits into mma.tf32) — no CVT.
// ============================================================
__global__ __launch_bounds__(256) void k1_mma(
    const int* __restrict__ tokens, const float* __restrict__ emb,
    const float* __restrict__ Wf, const float* __restrict__ bfv,
    const float* __restrict__ Wb, const float* __restrict__ bbv)
{
    extern __shared__ unsigned sm_u[];
    unsigned* As = sm_u;
    unsigned* Bs = sm_u + 8 * ACH;
    __shared__ int tk[128];

    const int tid  = threadIdx.x;
    const int lane = tid & 31;
    const int w    = tid >> 5;
    const int wm   = w >> 2;
    const int wn   = w & 3;
    const int row0 = blockIdx.y * 128;
    const int t    = row0 >> 9;
    const int b0   = row0 & 511;
    const int coff = blockIdx.x * 128;

    if (tid < 128) tk[tid] = tokens[row0 + tid];

    const bool fwd = (coff < G3);
    const float* Wsrc = fwd ? Wf : Wb;
    const float* bsrc = fwd ? bfv : bbv;
    const int cbase = fwd ? coff : (coff - G3);

    float acc[4][4][4];
    #pragma unroll
    for (int i = 0; i < 4; i++)
        #pragma unroll
        for (int j = 0; j < 4; j++)
            #pragma unroll
            for (int q = 0; q < 4; q++) acc[i][j][q] = 0.f;

    const int fl = tid & 15;
    const int rr = tid >> 4;

    for (int ks = 0; ks < 5; ks++) {
        const int kg4 = ks * 64 + fl * 4;
        const bool kv = (kg4 < EMBD);
        __syncthreads();
        #pragma unroll
        for (int rp = 0; rp < 8; rp++) {
            const int r = rp * 16 + rr;
            float4 v = make_float4(0.f, 0.f, 0.f, 0.f);
            if (kv) v = *(const float4*)(emb + (ll)tk[r] * EMBD + kg4);
            As[a_off(r, fl * 4 + 0)] = __float_as_uint(v.x);
            As[a_off(r, fl * 4 + 1)] = __float_as_uint(v.y);
            As[a_off(r, fl * 4 + 2)] = __float_as_uint(v.z);
            As[a_off(r, fl * 4 + 3)] = __float_as_uint(v.w);
        }
        #pragma unroll
        for (int cp = 0; cp < 8; cp++) {
            const int c = cp * 16 + rr;
            float4 v = make_float4(0.f, 0.f, 0.f, 0.f);
            if (kv) v = *(const float4*)(Wsrc + (ll)(cbase + c) * EMBD + kg4);
            Bs[b_off(c, fl * 4 + 0)] = __float_as_uint(v.x);
            Bs[b_off(c, fl * 4 + 1)] = __float_as_uint(v.y);
            Bs[b_off(c, fl * 4 + 2)] = __float_as_uint(v.z);
            Bs[b_off(c, fl * 4 + 3)] = __float_as_uint(v.w);
        }
        __syncthreads();
        #pragma unroll
        for (int ck = 0; ck < 8; ck++) {
            unsigned a[4][4], b[4][2];
            #pragma unroll
            for (int i = 0; i < 4; i++) {
                uint4 av = *(const uint4*)(As + ck * ACH + (wm * 4 + i) * 128 + lane * 4);
                a[i][0] = av.x; a[i][1] = av.y; a[i][2] = av.z; a[i][3] = av.w;
            }
            #pragma unroll
            for (int j = 0; j < 4; j++) {
                uint2 bv = *(const uint2*)(Bs + ck * BCH + (wn * 4 + j) * 64 + lane * 2);
                b[j][0] = bv.x; b[j][1] = bv.y;
            }
            #pragma unroll
            for (int i = 0; i < 4; i++)
                #pragma unroll
                for (int j = 0; j < 4; j++)
                    mma_tf32(acc[i][j], a[i], b[j]);
        }
    }

    const int tb = TT - 1 - t;
    #pragma unroll
    for (int j = 0; j < 4; j++) {
        const int cl = cbase + wn * 32 + j * 8 + 2 * (lane & 3);
        const float bv0 = bsrc[cl], bv1 = bsrc[cl + 1];
        #pragma unroll
        for (int i = 0; i < 4; i++) {
            const int b_lo = b0 + wm * 64 + i * 16 + (lane >> 2);
            float2 vlo = make_float2(acc[i][j][0] + bv0, acc[i][j][1] + bv1);
            float2 vhi = make_float2(acc[i][j][2] + bv0, acc[i][j][3] + bv1);
            if (fwd) {
                *(float2*)&g_xp_f[((ll)t * BB + b_lo) * G3 + cl] = vlo;
                *(float2*)&g_xp_f[((ll)t * BB + b_lo + 8) * G3 + cl] = vhi;
            } else {
                *(float2*)&g_xp_b[((ll)tb * BB + b_lo) * G3 + cl] = vlo;
                *(float2*)&g_xp_b[((ll)tb * BB + b_lo + 8) * G3 + cl] = vhi;
            }
        }
    }
}

// ============================================================
// K2: GRU scan via tf32 MMA. xp prefetched one step ahead,
// split accumulators, W_hh 6 kt in regs + 10 kt in smem.
// ============================================================
__global__ __launch_bounds__(256, 1) void k2_mma(
    const float* __restrict__ hidden,
    const float* __restrict__ Whh_f, const float* __restrict__ bhh_f,
    const float* __restrict__ Whh_b, const float* __restrict__ bhh_b)
{
    extern __shared__ float smf[];
    float* sB = smf;              // [w][kt-6 (10)][nt (6)][lane][2] = 30720 floats
    float* hA = smf + 30720;      // 2 x 2048 floats, layout [kt][lane][4regs]

    const int tid  = threadIdx.x;
    const int lane = tid & 31;
    const int w    = tid >> 5;          // 0..7 : k-slice [16w,16w+16)
    const int dir  = blockIdx.x >> 6;
    const int b0   = (blockIdx.x & 63) * 8;

    const float* Whh = dir ? Whh_b : Whh_f;
    const float* bhh = dir ? bhh_b : bhh_f;
    const float* xp  = dir ? g_xp_b : g_xp_f;
    float* ys        = dir ? g_ys_b : g_ys_f;

    const int m  = lane >> 2;           // real batch row 0..7
    const int q  = lane & 3;
    const int ks = w * 16;

    int gbase[6];
    gbase[0] = ks;       gbase[1] = ks + 8;
    gbase[2] = 128 + ks; gbase[3] = 128 + ks + 8;
    gbase[4] = 256 + ks; gbase[5] = 256 + ks + 8;

    // B-frags ktiles 0..5 in registers
    unsigned breg[6][6][2];
    #pragma unroll
    for (int kt = 0; kt < 6; kt++)
        #pragma unroll
        for (int nt = 0; nt < 6; nt++) {
            const float* wr = Whh + (ll)(gbase[nt] + m) * HH + kt * 8 + q;
            breg[kt][nt][0] = f2tf32(wr[0]);
            breg[kt][nt][1] = f2tf32(wr[4]);
        }
    // B-frags ktiles 6..15 into smem
    #pragma unroll
    for (int kt = 6; kt < 16; kt++)
        #pragma unroll
        for (int nt = 0; nt < 6; nt++) {
            const float* wr = Whh + (ll)(gbase[nt] + m) * HH + kt * 8 + q;
            float* d = sB + (((w * 10 + (kt - 6)) * 6 + nt) * 32 + lane) * 2;
            d[0] = __uint_as_float(f2tf32(wr[0]));
            d[1] = __uint_as_float(f2tf32(wr[4]));
        }

    float bh[3][4];
    #pragma unroll
    for (int g = 0; g < 3; g++)
        #pragma unroll
        for (int p = 0; p < 2; p++) {
            const float2 v = *(const float2*)(bhh + g * 128 + ks + p * 8 + q * 2);
            bh[g][p * 2 + 0] = v.x;
            bh[g][p * 2 + 1] = v.y;
        }

    // zero both h_A buffers (pad rows must stay 0 forever)
    for (int i = tid; i < 4096; i += 256) hA[30720 - 30720 + 30720 + i - 30720] = 0.f;  // keep simple below
    // (rewritten clearly)
    for (int i = tid; i < 4096; i += 256) hA[i] = 0.f;
    __syncthreads();

    float hold[4];
    #pragma unroll
    for (int p = 0; p < 2; p++) {
        const float2 v = *(const float2*)(hidden + ((ll)dir * BB + b0 + m) * HH + ks + p * 8 + q * 2);
        hold[p * 2 + 0] = v.x;
        hold[p * 2 + 1] = v.y;
        #pragma unroll
        for (int d_ = 0; d_ < 2; d_++) {
            const int k = ks + p * 8 + q * 2 + d_;
            hA[(k >> 3) * 128 + ((m << 2) | (k & 3)) * 4 + ((k & 4) ? 2 : 0)]
                = __uint_as_float(f2tf32(hold[p * 2 + d_]));
        }
    }
    __syncthreads();

    // preload xp for t=0
    float xv[3][4], xvn[3][4];
    #pragma unroll
    for (int g = 0; g < 3; g++)
        #pragma unroll
        for (int p = 0; p < 2; p++) {
            const float2 v = *(const float2*)(xp + ((ll)0 * BB + b0 + m) * G3 + g * 128 + ks + p * 8 + q * 2);
            xv[g][p * 2 + 0] = v.x;
            xv[g][p * 2 + 1] = v.y;
        }

    for (int t = 0; t < TT; t++) {
        const float* hAc = hA + (t & 1) * 2048;
        float* hAn       = hA + ((t + 1) & 1) * 2048;

        // prefetch xp for t+1 (consumed next iteration — DRAM latency hidden)
        const int tn = (t + 1 < TT) ? (t + 1) : t;
        #pragma unroll
        for (int g = 0; g < 3; g++)
            #pragma unroll
            for (int p = 0; p < 2; p++) {
                const float2 v = *(const float2*)(xp + ((ll)tn * BB + b0 + m) * G3 + g * 128 + ks + p * 8 + q * 2);
                xvn[g][p * 2 + 0] = v.x;
                xvn[g][p * 2 + 1] = v.y;
            }

        float acc0[6][4], acc1[6][4];
        #pragma unroll
        for (int nt = 0; nt < 6; nt++)
            #pragma unroll
            for (int c = 0; c < 4; c++) { acc0[nt][c] = 0.f; acc1[nt][c] = 0.f; }

        #pragma unroll
        for (int kt = 0; kt < 16; kt++) {
            uint4 av = *(const uint4*)(hAc + kt * 128 + lane * 4);
            unsigned a[4] = {av.x, av.y, av.z, av.w};
            if (kt < 6) {
                #pragma unroll
                for (int nt = 0; nt < 6; nt++)
                    mma_tf32(acc0[nt], a, breg[kt][nt]);
            } else {
                #pragma unroll
                for (int nt = 0; nt < 6; nt++) {
                    const float2 bv = *(const float2*)(sB + (((w * 10 + (kt - 6)) * 6 + nt) * 32 + lane) * 2);
                    unsigned b[2] = {__float_as_uint(bv.x), __float_as_uint(bv.y)};
                    mma_tf32(acc1[nt], a, b);
                }
            }
        }

        // register-local GRU cell epilogue
        float hnew[4];
        #pragma unroll
        for (int p = 0; p < 2; p++)
            #pragma unroll
            for (int d_ = 0; d_ < 2; d_++) {
                const int i = p * 2 + d_;
                const float hr = acc0[p][d_] + acc1[p][d_];
                const float hz = acc0[2 + p][d_] + acc1[2 + p][d_];
                const float hn = acc0[4 + p][d_] + acc1[4 + p][d_];
                const float rs = xv[0][i] + hr + bh[0][i];
                const float zs = xv[1][i] + hz + bh[1][i];
                const float rg = __fdividef(1.f, 1.f + __expf(-rs));
                const float zg = __fdividef(1.f, 1.f + __expf(-zs));
                const float a_ = xv[2][i] + rg * (hn + bh[2][i]);
                const float e  = __expf(2.f * a_);
                const float n_ = 1.f - __fdividef(2.f, e + 1.f);
                hnew[i] = (1.f - zg) * n_ + zg * hold[i];
                hold[i] = hnew[i];
                const int k = ks + p * 8 + q * 2 + d_;
                hAn[(k >> 3) * 128 + ((m << 2) | (k & 3)) * 4 + ((k & 4) ? 2 : 0)]
                    = __uint_as_float(f2tf32(hnew[i]));
            }

        #pragma unroll
        for (int p = 0; p < 2; p++)
            *(float2*)(ys + ((ll)t * BB + b0 + m) * HH + ks + p * 8 + q * 2)
                = make_float2(hnew[p * 2], hnew[p * 2 + 1]);

        // rotate prefetched xp into place
        #pragma unroll
        for (int g = 0; g < 3; g++)
            #pragma unroll
            for (int i = 0; i < 4; i++) xv[g][i] = xvn[g][i];

        __syncthreads();
    }
}

// ============================================================
// K3: hyp = tanh(f @ attn2_W^T + b) via tf32 mma (RZ staging)
// ============================================================
__global__ __launch_bounds__(256) void k3_mma(
    const float* __restrict__ W, const float* __restrict__ bias)
{
    extern __shared__ unsigned sm_u[];
    unsigned* As = sm_u;
    unsigned* Bs = sm_u + 8 * ACH;

    const int tid  = threadIdx.x;
    const int lane = tid & 31;
    const int w    = tid >> 5;
    const int wm   = w >> 2;
    const int wn   = w & 3;
    const int row0 = blockIdx.y * 128;
    const int t    = row0 >> 9;
    const int b0   = row0 & 511;
    const int tb   = TT - 1 - t;
    const int coff = blockIdx.x * 128;

    float acc[4][4][4];
    #pragma unroll
    for (int i = 0; i < 4; i++)
        #pragma unroll
        for (int j = 0; j < 4; j++)
            #pragma unroll
            for (int q = 0; q < 4; q++) acc[i][j][q] = 0.f;

    const int fl = tid & 15;
    const int rr = tid >> 4;

    for (int ks = 0; ks < 4; ks++) {
        const int kg4 = ks * 64 + fl * 4;
        __syncthreads();
        const float* ysrc = (ks < 2) ? (g_ys_f + (ll)t * BB * HH)
                                     : (g_ys_b + (ll)tb * BB * HH);
        const int kk4 = (ks < 2) ? kg4 : (kg4 - HH);
        #pragma unroll
        for (int rp = 0; rp < 8; rp++) {
            const int r = rp * 16 + rr;
            float4 v = *(const float4*)(ysrc + (ll)(b0 + r) * HH + kk4);
            As[a_off(r, fl * 4 + 0)] = __float_as_uint(v.x);
            As[a_off(r, fl * 4 + 1)] = __float_as_uint(v.y);
            As[a_off(r, fl * 4 + 2)] = __float_as_uint(v.z);
            As[a_off(r, fl * 4 + 3)] = __float_as_uint(v.w);
        }
        #pragma unroll
        for (int cp = 0; cp < 8; cp++) {
            const int c = cp * 16 + rr;
            float4 v = *(const float4*)(W + (ll)(coff + c) * DD + kg4);
            Bs[b_off(c, fl * 4 + 0)] = __float_as_uint(v.x);
            Bs[b_off(c, fl * 4 + 1)] = __float_as_uint(v.y);
            Bs[b_off(c, fl * 4 + 2)] = __float_as_uint(v.z);
            Bs[b_off(c, fl * 4 + 3)] = __float_as_uint(v.w);
        }
        __syncthreads();
        #pragma unroll
        for (int ck = 0; ck < 8; ck++) {
            unsigned a[4][4], b[4][2];
            #pragma unroll
            for (int i = 0; i < 4; i++) {
                uint4 av = *(const uint4*)(As + ck * ACH + (wm * 4 + i) * 128 + lane * 4);
                a[i][0] = av.x; a[i][1] = av.y; a[i][2] = av.z; a[i][3] = av.w;
            }
            #pragma unroll
            for (int j = 0; j < 4; j++) {
                uint2 bv = *(const uint2*)(Bs + ck * BCH + (wn * 4 + j) * 64 + lane * 2);
                b[j][0] = bv.x; b[j][1] = bv.y;
            }
            #pragma unroll
            for (int i = 0; i < 4; i++)
                #pragma unroll
                for (int j = 0; j < 4; j++)
                    mma_tf32(acc[i][j], a[i], b[j]);
        }
    }

    #pragma unroll
    for (int j = 0; j < 4; j++) {
        const int n = coff + wn * 32 + j * 8 + 2 * (lane & 3);
        const float bv0 = bias[n], bv1 = bias[n + 1];
        #pragma unroll
        for (int i = 0; i < 4; i++) {
            const int m_lo = row0 + wm * 64 + i * 16 + (lane >> 2);
            float v[4] = {acc[i][j][0] + bv0, acc[i][j][1] + bv1,
                          acc[i][j][2] + bv0, acc[i][j][3] + bv1};
            #pragma unroll
            for (int qq = 0; qq < 4; qq++) {
                const float e = __expf(2.f * v[qq]);
                v[qq] = 1.f - __fdividef(2.f, e + 1.f);
            }
            *(float2*)&g_hyp[(ll)m_lo * DD + n] = make_float2(v[0], v[1]);
            *(float2*)&g_hyp[(ll)(m_lo + 8) * DD + n] = make_float2(v[2], v[3]);
        }
    }
}

// ============================================================
// K34: fused ||f||^2 + hyperbolic score, one warp per (t,b) row
// ============================================================
__global__ __launch_bounds__(256) void k34_scores(
    const float* __restrict__ cent, const float* __restrict__ beta)
{
    const int row  = blockIdx.x * 8 + (threadIdx.x >> 5);
    const int lane = threadIdx.x & 31;
    const int t = row >> 9, b = row & 511;
    const float* yf = g_ys_f + ((ll)t * BB + b) * HH;
    const float* yb = g_ys_b + ((ll)(TT - 1 - t) * BB + b) * HH;
    const float* hy = g_hyp + (ll)row * DD;

    float s = 0.f, h2 = 0.f, cd = 0.f;
    #pragma unroll
    for (int i = 0; i < 4; i++) {
        const float a = yf[lane + 32 * i];
        const float c = yb[lane + 32 * i];
        s += a * a + c * c;
    }
    #pragma unroll
    for (int i = 0; i < 8; i++) {
        const float hv = hy[lane + 32 * i];
        const float cv = cent[lane + 32 * i];
        h2 += hv * hv; cd += hv * cv;
    }
    #pragma unroll
    for (int o = 16; o; o >>= 1) {
        s  += __shfl_xor_sync(0xffffffffu, s, o);
        h2 += __shfl_xor_sync(0xffffffffu, h2, o);
        cd += __shfl_xor_sync(0xffffffffu, cd, o);
    }
    if (lane == 0) {
        g_rr2[row] = s;
        const float rh = sqrtf(h2);
        float pm = coshf(rh) * g_cc[0] - (sinhf(rh) / rh) * g_cc[1] * cd;
        pm = fminf(fmaxf(pm, 1.f + EPSF), 1e16f);
        const float dist = logf(pm) + log1pf(sqrtf(pm * pm - 1.f + EPSF) / pm);
        g_scores[row] = -beta[0] * dist - 1.f;
    }
}

// ============================================================
// K5: softmax x gamma Einstein-midpoint pooling + h_output
// ============================================================
__global__ __launch_bounds__(256) void k5_pool(float* __restrict__ out)
{
    __shared__ float wk[128];
    __shared__ float red[128];
    const int b = blockIdx.x, tid = threadIdx.x;

    float s = -1e30f;
    if (tid < 128) {
        s = g_scores[tid * BB + b];
        red[tid] = s;
    }
    __syncthreads();
    for (int o = 64; o; o >>= 1) {
        if (tid < o) red[tid] = fmaxf(red[tid], red[tid + o]);
        __syncthreads();
    }
    const float smax = red[0];
    __syncthreads();

    float myw = 0.f, kf = 0.f;
    if (tid < 128) {
        const float rr = sqrtf(g_rr2[tid * BB + b]);
        const float sh = sinhf(rr), ch = coshf(rr);
        const float th = sh / ch;
        float gsq = 1.f - th * th;
        gsq = fminf(fmaxf(gsq, EPSF), 1.f - EPSF);
        float gam = 1.f / sqrtf(gsq);
        gam = fminf(fmaxf(gam, 1.f + EPSF), 1e16f);
        myw = __expf(s - smax) * gam;
        kf = th / rr;
        red[tid] = myw;
    }
    __syncthreads();
    for (int o = 64; o; o >>= 1) {
        if (tid < o) red[tid] += red[tid + o];
        __syncthreads();
    }
    const float wsum = red[0];
    if (tid < 128) wk[tid] = (myw / wsum) * kf;
    __syncthreads();

    float acc = 0.f;
    if (tid < 128) {
        for (int t = 0; t < TT; t++)
            acc += wk[t] * g_ys_f[((ll)t * BB + b) * HH + tid];
    } else {
        const int k = tid - 128;
        for (int t = 0; t < TT; t++)
            acc += wk[t] * g_ys_b[((ll)(TT - 1 - t) * BB + b) * HH + k];
    }
    out[b * DD + tid] = acc;

    float* hout = out + BB * DD;
    if (tid < 128) {
        hout[b * HH + tid] = g_ys_f[((ll)(TT - 1) * BB + b) * HH + tid];
    } else {
        const int k = tid - 128;
        hout[BB * HH + b * HH + k] = g_ys_b[((ll)(TT - 1) * BB + b) * HH + k];
    }
}

// ============================================================
extern "C" void kernel_launch(void* const* d_in, const int* in_sizes, int n_in,
                              void* d_out, int out_size)
{
    const int*   tokens = (const int*)d_in[0];
    const float* hidden = (const float*)d_in[1];
    const float* emb    = (const float*)d_in[2];
    const float* W_ih_f = (const float*)d_in[3];
    const float* W_hh_f = (const float*)d_in[4];
    const float* b_ih_f = (const float*)d_in[5];
    const float* b_hh_f = (const float*)d_in[6];
    const float* W_ih_b = (const float*)d_in[7];
    const float* W_hh_b = (const float*)d_in[8];
    const float* b_ih_b = (const float*)d_in[9];
    const float* b_hh_b = (const float*)d_in[10];
    const float* attn2W = (const float*)d_in[11];
    const float* attn2b = (const float*)d_in[12];
    const float* cent   = (const float*)d_in[13];
    const float* beta   = (const float*)d_in[14];
    float* out = (float*)d_out;

    cudaFuncSetAttribute(k1_mma, cudaFuncAttributeMaxDynamicSharedMemorySize, MMA_SMEM);
    cudaFuncSetAttribute(k2_mma, cudaFuncAttributeMaxDynamicSharedMemorySize, K2_SMEM);
    cudaFuncSetAttribute(k3_mma, cudaFuncAttributeMaxDynamicSharedMemorySize, MMA_SMEM);

    // k0 x2 so the ncu capture slot (4th launch) = k2_mma
    k0_cent<<<1, 32>>>(cent);
    k0_cent<<<1, 32>>>(cent);
    k1_mma<<<dim3(6, 512), 256, MMA_SMEM>>>(tokens, emb, W_ih_f, b_ih_f, W_ih_b, b_ih_b);
    k2_mma<<<128, 256, K2_SMEM>>>(hidden, W_hh_f, b_hh_f, W_hh_b, b_hh_b);
    k3_mma<<<dim3(2, 512), 256, MMA_SMEM>>>(attn2W, attn2b);
    k34_scores<<<8192, 256>>>(cent, beta);
    k5_pool<<<512, 256>>>(out);
}

// round 14
// speedup vs baseline: 1.3823x; 1.3823x over previous
#include <cuda_runtime.h>
#include <math.h>

#define TT   128
#define BB   512
#define HH   128
#define EMBD 300
#define DD   256
#define G3   384
#define EPSF 1e-7f

typedef long long ll;

__device__ float g_xp_f[TT * BB * G3];
__device__ float g_xp_b[TT * BB * G3];
__device__ float g_ys_f[TT * BB * HH];
__device__ float g_ys_b[TT * BB * HH];
__device__ float g_hyp[TT * BB * DD];
__device__ float g_scores[TT * BB];
__device__ float g_rr2[TT * BB];
__device__ float g_cc[2];   // [cosh(rc), sinh(rc)/rc]

// ---- tf32 helpers ----
__device__ __forceinline__ unsigned f2tf32(float v) {      // RNA
    unsigned u;
    asm("cvt.rna.tf32.f32 %0, %1;" : "=r"(u) : "f"(v));
    return u;
}
__device__ __forceinline__ void mma_tf32(float* c, const unsigned* a, const unsigned* b) {
    asm volatile(
        "mma.sync.aligned.m16n8k8.row.col.f32.tf32.tf32.f32 "
        "{%0,%1,%2,%3}, {%4,%5,%6,%7}, {%8,%9}, {%0,%1,%2,%3};"
        : "+f"(c[0]), "+f"(c[1]), "+f"(c[2]), "+f"(c[3])
        : "r"(a[0]), "r"(a[1]), "r"(a[2]), "r"(a[3]), "r"(b[0]), "r"(b[1]));
}

__device__ __forceinline__ void cpa16(float* dst_smem, const void* src, bool valid) {
    unsigned d = (unsigned)__cvta_generic_to_shared(dst_smem);
    int sz = valid ? 16 : 0;          // src-size 0 => 16B zero-fill
    asm volatile("cp.async.cg.shared.global [%0], [%1], 16, %2;"
                 :: "r"(d), "l"(src), "r"(sz) : "memory");
}

// ---- K3 fragment-major layout ----
#define ACH 1032
#define BCH 1032
#define MMA_SMEM ((8 * ACH + 8 * BCH) * 4)   // 66,048 B

__device__ __forceinline__ int a_off(int r, int kk) {
    return (kk >> 3) * ACH + (r >> 4) * 128 + ((((r & 7) << 2) | (kk & 3)) << 2)
           + ((r >> 3) & 1) + (((kk >> 2) & 1) << 1);
}
__device__ __forceinline__ int b_off(int c, int kk) {
    return (kk >> 3) * BCH + (c >> 3) * 64 + ((((c & 7) << 2) | (kk & 3)) << 1)
           + ((kk >> 2) & 1);
}

// K1: double-buffered reg-major smem, K=32 slices: 2 x (A 4096 + B 4096) floats
#define K1_SMEM (2 * 8192 * 4)       // 65,536 B -> 2 blocks/SM

// K2 smem: B-frags ktiles 6..15 (10 kt) + double-buffered h_A
#define K2_SMEM (122880 + 16384)     // 139,264 B

// ============================================================
// K0: centroid constants — idempotent
// ============================================================
__global__ void k0_cent(const float* __restrict__ cent)
{
    const int lane = threadIdx.x;
    float c2 = 0.f;
    #pragma unroll
    for (int i = 0; i < 8; i++) {
        const float cv = cent[lane + 32 * i];
        c2 += cv * cv;
    }
    #pragma unroll
    for (int o = 16; o; o >>= 1) c2 += __shfl_xor_sync(0xffffffffu, c2, o);
    if (lane == 0) {
        const float rc = sqrtf(c2);
        g_cc[0] = coshf(rc);
        g_cc[1] = sinhf(rc) / rc;
    }
}

// ============================================================
// K1: embed gather + input projections via tf32 mma.
// cp.async 2-deep pipeline, K=32 slices, 64KB smem (2 blocks/SM).
// ============================================================
__global__ __launch_bounds__(256, 2) void k1_mma(
    const int* __restrict__ tokens, const float* __restrict__ emb,
    const float* __restrict__ Wf, const float* __restrict__ bfv,
    const float* __restrict__ Wb, const float* __restrict__ bbv)
{
    extern __shared__ float smf[];
    __shared__ int tk[128];

    const int tid  = threadIdx.x;
    const int lane = tid & 31;
    const int w    = tid >> 5;
    const int wm   = w >> 2;            // 0..1 : 64 rows
    const int wn   = w & 3;             // 0..3 : 32 cols
    const int row0 = blockIdx.y * 128;
    const int t    = row0 >> 9;
    const int b0   = row0 & 511;
    const int coff = blockIdx.x * 128;

    const bool fwd = (coff < G3);
    const float* Wsrc = fwd ? Wf : Wb;
    const float* bsrc = fwd ? bfv : bbv;
    const int cbase = fwd ? coff : (coff - G3);

    if (tid < 128) tk[tid] = tokens[row0 + tid];
    __syncthreads();

    const int fl    = tid & 7;          // 16B chunk along k32 slice
    const int rr    = tid >> 3;         // 0..31 rows/cols per pass
    const int ktile = fl >> 1;          // 0..3
    const int khalf = fl & 1;           // k%8 >= 4 ?

    // stage slice s into buffer s&1 (A: [kt][mtile][areg][lane], B: [kt][ntile][breg][lane])
    auto stage = [&](int s) {
        float* A = smf + (s & 1) * 8192;
        float* B = A + 4096;
        const int kg4 = s * 32 + fl * 4;
        const bool kv = (kg4 < EMBD);   // EMBD%4==0 -> all-or-nothing per chunk
        #pragma unroll
        for (int rp = 0; rp < 4; rp++) {
            const int r = rp * 32 + rr;
            const int areg = ((r & 15) >> 3) + khalf * 2;
            cpa16(A + ktile * 1024 + (r >> 4) * 128 + areg * 32 + (r & 7) * 4,
                  emb + (ll)tk[r] * EMBD + kg4, kv);
        }
        #pragma unroll
        for (int cp = 0; cp < 4; cp++) {
            const int c = cp * 32 + rr;
            cpa16(B + ktile * 1024 + (c >> 3) * 64 + khalf * 32 + (c & 7) * 4,
                  Wsrc + (ll)(cbase + c) * EMBD + kg4, kv);
        }
        asm volatile("cp.async.commit_group;" ::: "memory");
    };

    float acc[4][4][4];
    #pragma unroll
    for (int i = 0; i < 4; i++)
        #pragma unroll
        for (int j = 0; j < 4; j++)
            #pragma unroll
            for (int q = 0; q < 4; q++) acc[i][j][q] = 0.f;

    stage(0);

    for (int s = 0; s < 10; s++) {
        if (s + 1 < 10) {
            stage(s + 1);
            asm volatile("cp.async.wait_group 1;" ::: "memory");
        } else {
            asm volatile("cp.async.wait_group 0;" ::: "memory");
        }
        __syncthreads();

        const unsigned* Au = (const unsigned*)(smf + (s & 1) * 8192);
        const unsigned* Bu = Au + 4096;

        #pragma unroll
        for (int ck = 0; ck < 4; ck++) {
            unsigned a[4][4], b[4][2];
            #pragma unroll
            for (int i = 0; i < 4; i++) {
                const unsigned* ap = Au + ck * 1024 + (wm * 4 + i) * 128 + lane;
                a[i][0] = ap[0]; a[i][1] = ap[32]; a[i][2] = ap[64]; a[i][3] = ap[96];
            }
            #pragma unroll
            for (int j = 0; j < 4; j++) {
                const unsigned* bp = Bu + ck * 1024 + (wn * 4 + j) * 64 + lane;
                b[j][0] = bp[0]; b[j][1] = bp[32];
            }
            #pragma unroll
            for (int i = 0; i < 4; i++)
                #pragma unroll
                for (int j = 0; j < 4; j++)
                    mma_tf32(acc[i][j], a[i], b[j]);
        }
        __syncthreads();   // before next stage overwrites this buffer
    }

    const int tb = TT - 1 - t;
    #pragma unroll
    for (int j = 0; j < 4; j++) {
        const int cl = cbase + wn * 32 + j * 8 + 2 * (lane & 3);
        const float bv0 = bsrc[cl], bv1 = bsrc[cl + 1];
        #pragma unroll
        for (int i = 0; i < 4; i++) {
            const int b_lo = b0 + wm * 64 + i * 16 + (lane >> 2);
            float2 vlo = make_float2(acc[i][j][0] + bv0, acc[i][j][1] + bv1);
            float2 vhi = make_float2(acc[i][j][2] + bv0, acc[i][j][3] + bv1);
            if (fwd) {
                *(float2*)&g_xp_f[((ll)t * BB + b_lo) * G3 + cl] = vlo;
                *(float2*)&g_xp_f[((ll)t * BB + b_lo + 8) * G3 + cl] = vhi;
            } else {
                *(float2*)&g_xp_b[((ll)tb * BB + b_lo) * G3 + cl] = vlo;
                *(float2*)&g_xp_b[((ll)tb * BB + b_lo + 8) * G3 + cl] = vhi;
            }
        }
    }
}

// ============================================================
// K2: GRU scan via tf32 MMA (R13 form: xp prefetch, split acc,
// W_hh 6 kt regs + 10 kt smem).
// ============================================================
__global__ __launch_bounds__(256, 1) void k2_mma(
    const float* __restrict__ hidden,
    const float* __restrict__ Whh_f, const float* __restrict__ bhh_f,
    const float* __restrict__ Whh_b, const float* __restrict__ bhh_b)
{
    extern __shared__ float smf[];
    float* sB = smf;              // [w][kt-6 (10)][nt (6)][lane][2]
    float* hA = smf + 30720;      // 2 x 2048 floats

    const int tid  = threadIdx.x;
    const int lane = tid & 31;
    const int w    = tid >> 5;
    const int dir  = blockIdx.x >> 6;
    const int b0   = (blockIdx.x & 63) * 8;

    const float* Whh = dir ? Whh_b : Whh_f;
    const float* bhh = dir ? bhh_b : bhh_f;
    const float* xp  = dir ? g_xp_b : g_xp_f;
    float* ys        = dir ? g_ys_b : g_ys_f;

    const int m  = lane >> 2;
    const int q  = lane & 3;
    const int ks = w * 16;

    int gbase[6];
    gbase[0] = ks;       gbase[1] = ks + 8;
    gbase[2] = 128 + ks; gbase[3] = 128 + ks + 8;
    gbase[4] = 256 + ks; gbase[5] = 256 + ks + 8;

    unsigned breg[6][6][2];
    #pragma unroll
    for (int kt = 0; kt < 6; kt++)
        #pragma unroll
        for (int nt = 0; nt < 6; nt++) {
            const float* wr = Whh + (ll)(gbase[nt] + m) * HH + kt * 8 + q;
            breg[kt][nt][0] = f2tf32(wr[0]);
            breg[kt][nt][1] = f2tf32(wr[4]);
        }
    #pragma unroll
    for (int kt = 6; kt < 16; kt++)
        #pragma unroll
        for (int nt = 0; nt < 6; nt++) {
            const float* wr = Whh + (ll)(gbase[nt] + m) * HH + kt * 8 + q;
            float* d = sB + (((w * 10 + (kt - 6)) * 6 + nt) * 32 + lane) * 2;
            d[0] = __uint_as_float(f2tf32(wr[0]));
            d[1] = __uint_as_float(f2tf32(wr[4]));
        }

    float bh[3][4];
    #pragma unroll
    for (int g = 0; g < 3; g++)
        #pragma unroll
        for (int p = 0; p < 2; p++) {
            const float2 v = *(const float2*)(bhh + g * 128 + ks + p * 8 + q * 2);
            bh[g][p * 2 + 0] = v.x;
            bh[g][p * 2 + 1] = v.y;
        }

    for (int i = tid; i < 4096; i += 256) hA[i] = 0.f;
    __syncthreads();

    float hold[4];
    #pragma unroll
    for (int p = 0; p < 2; p++) {
        const float2 v = *(const float2*)(hidden + ((ll)dir * BB + b0 + m) * HH + ks + p * 8 + q * 2);
        hold[p * 2 + 0] = v.x;
        hold[p * 2 + 1] = v.y;
        #pragma unroll
        for (int d_ = 0; d_ < 2; d_++) {
            const int k = ks + p * 8 + q * 2 + d_;
            hA[(k >> 3) * 128 + ((m << 2) | (k & 3)) * 4 + ((k & 4) ? 2 : 0)]
                = __uint_as_float(f2tf32(hold[p * 2 + d_]));
        }
    }
    __syncthreads();

    float xv[3][4], xvn[3][4];
    #pragma unroll
    for (int g = 0; g < 3; g++)
        #pragma unroll
        for (int p = 0; p < 2; p++) {
            const float2 v = *(const float2*)(xp + ((ll)(b0 + m)) * G3 + g * 128 + ks + p * 8 + q * 2);
            xv[g][p * 2 + 0] = v.x;
            xv[g][p * 2 + 1] = v.y;
        }

    for (int t = 0; t < TT; t++) {
        const float* hAc = hA + (t & 1) * 2048;
        float* hAn       = hA + ((t + 1) & 1) * 2048;

        const int tn = (t + 1 < TT) ? (t + 1) : t;
        #pragma unroll
        for (int g = 0; g < 3; g++)
            #pragma unroll
            for (int p = 0; p < 2; p++) {
                const float2 v = *(const float2*)(xp + ((ll)tn * BB + b0 + m) * G3 + g * 128 + ks + p * 8 + q * 2);
                xvn[g][p * 2 + 0] = v.x;
                xvn[g][p * 2 + 1] = v.y;
            }

        float acc0[6][4], acc1[6][4];
        #pragma unroll
        for (int nt = 0; nt < 6; nt++)
            #pragma unroll
            for (int c = 0; c < 4; c++) { acc0[nt][c] = 0.f; acc1[nt][c] = 0.f; }

        #pragma unroll
        for (int kt = 0; kt < 16; kt++) {
            uint4 av = *(const uint4*)(hAc + kt * 128 + lane * 4);
            unsigned a[4] = {av.x, av.y, av.z, av.w};
            if (kt < 6) {
                #pragma unroll
                for (int nt = 0; nt < 6; nt++)
                    mma_tf32(acc0[nt], a, breg[kt][nt]);
            } else {
                #pragma unroll
                for (int nt = 0; nt < 6; nt++) {
                    const float2 bv = *(const float2*)(sB + (((w * 10 + (kt - 6)) * 6 + nt) * 32 + lane) * 2);
                    unsigned b[2] = {__float_as_uint(bv.x), __float_as_uint(bv.y)};
                    mma_tf32(acc1[nt], a, b);
                }
            }
        }

        float hnew[4];
        #pragma unroll
        for (int p = 0; p < 2; p++)
            #pragma unroll
            for (int d_ = 0; d_ < 2; d_++) {
                const int i = p * 2 + d_;
                const float hr = acc0[p][d_] + acc1[p][d_];
                const float hz = acc0[2 + p][d_] + acc1[2 + p][d_];
                const float hn = acc0[4 + p][d_] + acc1[4 + p][d_];
                const float rs = xv[0][i] + hr + bh[0][i];
                const float zs = xv[1][i] + hz + bh[1][i];
                const float rg = __fdividef(1.f, 1.f + __expf(-rs));
                const float zg = __fdividef(1.f, 1.f + __expf(-zs));
                const float a_ = xv[2][i] + rg * (hn + bh[2][i]);
                const float e  = __expf(2.f * a_);
                const float n_ = 1.f - __fdividef(2.f, e + 1.f);
                hnew[i] = (1.f - zg) * n_ + zg * hold[i];
                hold[i] = hnew[i];
                const int k = ks + p * 8 + q * 2 + d_;
                hAn[(k >> 3) * 128 + ((m << 2) | (k & 3)) * 4 + ((k & 4) ? 2 : 0)]
                    = __uint_as_float(f2tf32(hnew[i]));
            }

        #pragma unroll
        for (int p = 0; p < 2; p++)
            *(float2*)(ys + ((ll)t * BB + b0 + m) * HH + ks + p * 8 + q * 2)
                = make_float2(hnew[p * 2], hnew[p * 2 + 1]);

        #pragma unroll
        for (int g = 0; g < 3; g++)
            #pragma unroll
            for (int i = 0; i < 4; i++) xv[g][i] = xvn[g][i];

        __syncthreads();
    }
}

// ============================================================
// K3: hyp = tanh(f @ attn2_W^T + b) via tf32 mma (RNA, R8 form)
// ============================================================
__global__ __launch_bounds__(256) void k3_mma(
    const float* __restrict__ W, const float* __restrict__ bias)
{
    extern __shared__ float smf[];
    unsigned* As = (unsigned*)smf;
    unsigned* Bs = As + 8 * ACH;

    const int tid  = threadIdx.x;
    const int lane = tid & 31;
    const int w    = tid >> 5;
    const int wm   = w >> 2;
    const int wn   = w & 3;
    const int row0 = blockIdx.y * 128;
    const int t    = row0 >> 9;
    const int b0   = row0 & 511;
    const int tb   = TT - 1 - t;
    const int coff = blockIdx.x * 128;

    float acc[4][4][4];
    #pragma unroll
    for (int i = 0; i < 4; i++)
        #pragma unroll
        for (int j = 0; j < 4; j++)
            #pragma unroll
            for (int q = 0; q < 4; q++) acc[i][j][q] = 0.f;

    const int fl = tid & 15;
    const int rr = tid >> 4;

    for (int ks = 0; ks < 4; ks++) {
        const int kg4 = ks * 64 + fl * 4;
        __syncthreads();
        const float* ysrc = (ks < 2) ? (g_ys_f + (ll)t * BB * HH)
                                     : (g_ys_b + (ll)tb * BB * HH);
        const int kk4 = (ks < 2) ? kg4 : (kg4 - HH);
        #pragma unroll
        for (int rp = 0; rp < 8; rp++) {
            const int r = rp * 16 + rr;
            float4 v = *(const float4*)(ysrc + (ll)(b0 + r) * HH + kk4);
            As[a_off(r, fl * 4 + 0)] = f2tf32(v.x);
            As[a_off(r, fl * 4 + 1)] = f2tf32(v.y);
            As[a_off(r, fl * 4 + 2)] = f2tf32(v.z);
            As[a_off(r, fl * 4 + 3)] = f2tf32(v.w);
        }
        #pragma unroll
        for (int cp = 0; cp < 8; cp++) {
            const int c = cp * 16 + rr;
            float4 v = *(const float4*)(W + (ll)(coff + c) * DD + kg4);
            Bs[b_off(c, fl * 4 + 0)] = f2tf32(v.x);
            Bs[b_off(c, fl * 4 + 1)] = f2tf32(v.y);
            Bs[b_off(c, fl * 4 + 2)] = f2tf32(v.z);
            Bs[b_off(c, fl * 4 + 3)] = f2tf32(v.w);
        }
        __syncthreads();
        #pragma unroll
        for (int ck = 0; ck < 8; ck++) {
            unsigned a[4][4], b[4][2];
            #pragma unroll
            for (int i = 0; i < 4; i++) {
                uint4 av = *(const uint4*)(As + ck * ACH + (wm * 4 + i) * 128 + lane * 4);
                a[i][0] = av.x; a[i][1] = av.y; a[i][2] = av.z; a[i][3] = av.w;
            }
            #pragma unroll
            for (int j = 0; j < 4; j++) {
                uint2 bv = *(const uint2*)(Bs + ck * BCH + (wn * 4 + j) * 64 + lane * 2);
                b[j][0] = bv.x; b[j][1] = bv.y;
            }
            #pragma unroll
            for (int i = 0; i < 4; i++)
                #pragma unroll
                for (int j = 0; j < 4; j++)
                    mma_tf32(acc[i][j], a[i], b[j]);
        }
    }

    #pragma unroll
    for (int j = 0; j < 4; j++) {
        const int n = coff + wn * 32 + j * 8 + 2 * (lane & 3);
        const float bv0 = bias[n], bv1 = bias[n + 1];
        #pragma unroll
        for (int i = 0; i < 4; i++) {
            const int m_lo = row0 + wm * 64 + i * 16 + (lane >> 2);
            float v[4] = {acc[i][j][0] + bv0, acc[i][j][1] + bv1,
                          acc[i][j][2] + bv0, acc[i][j][3] + bv1};
            #pragma unroll
            for (int qq = 0; qq < 4; qq++) {
                const float e = __expf(2.f * v[qq]);
                v[qq] = 1.f - __fdividef(2.f, e + 1.f);
            }
            *(float2*)&g_hyp[(ll)m_lo * DD + n] = make_float2(v[0], v[1]);
            *(float2*)&g_hyp[(ll)(m_lo + 8) * DD + n] = make_float2(v[2], v[3]);
        }
    }
}

// ============================================================
// K34: fused ||f||^2 + hyperbolic score, one warp per (t,b) row
// ============================================================
__global__ __launch_bounds__(256) void k34_scores(
    const float* __restrict__ cent, const float* __restrict__ beta)
{
    const int row  = blockIdx.x * 8 + (threadIdx.x >> 5);
    const int lane = threadIdx.x & 31;
    const int t = row >> 9, b = row & 511;
    const float* yf = g_ys_f + ((ll)t * BB + b) * HH;
    const float* yb = g_ys_b + ((ll)(TT - 1 - t) * BB + b) * HH;
    const float* hy = g_hyp + (ll)row * DD;

    float s = 0.f, h2 = 0.f, cd = 0.f;
    #pragma unroll
    for (int i = 0; i < 4; i++) {
        const float a = yf[lane + 32 * i];
        const float c = yb[lane + 32 * i];
        s += a * a + c * c;
    }
    #pragma unroll
    for (int i = 0; i < 8; i++) {
        const float hv = hy[lane + 32 * i];
        const float cv = cent[lane + 32 * i];
        h2 += hv * hv; cd += hv * cv;
    }
    #pragma unroll
    for (int o = 16; o; o >>= 1) {
        s  += __shfl_xor_sync(0xffffffffu, s, o);
        h2 += __shfl_xor_sync(0xffffffffu, h2, o);
        cd += __shfl_xor_sync(0xffffffffu, cd, o);
    }
    if (lane == 0) {
        g_rr2[row] = s;
        const float rh = sqrtf(h2);
        float pm = coshf(rh) * g_cc[0] - (sinhf(rh) / rh) * g_cc[1] * cd;
        pm = fminf(fmaxf(pm, 1.f + EPSF), 1e16f);
        const float dist = logf(pm) + log1pf(sqrtf(pm * pm - 1.f + EPSF) / pm);
        g_scores[row] = -beta[0] * dist - 1.f;
    }
}

// ============================================================
// K5: softmax x gamma Einstein-midpoint pooling + h_output
// ============================================================
__global__ __launch_bounds__(256) void k5_pool(float* __restrict__ out)
{
    __shared__ float wk[128];
    __shared__ float red[128];
    const int b = blockIdx.x, tid = threadIdx.x;

    float s = -1e30f;
    if (tid < 128) {
        s = g_scores[tid * BB + b];
        red[tid] = s;
    }
    __syncthreads();
    for (int o = 64; o; o >>= 1) {
        if (tid < o) red[tid] = fmaxf(red[tid], red[tid + o]);
        __syncthreads();
    }
    const float smax = red[0];
    __syncthreads();

    float myw = 0.f, kf = 0.f;
    if (tid < 128) {
        const float rr = sqrtf(g_rr2[tid * BB + b]);
        const float sh = sinhf(rr), ch = coshf(rr);
        const float th = sh / ch;
        float gsq = 1.f - th * th;
        gsq = fminf(fmaxf(gsq, EPSF), 1.f - EPSF);
        float gam = 1.f / sqrtf(gsq);
        gam = fminf(fmaxf(gam, 1.f + EPSF), 1e16f);
        myw = __expf(s - smax) * gam;
        kf = th / rr;
        red[tid] = myw;
    }
    __syncthreads();
    for (int o = 64; o; o >>= 1) {
        if (tid < o) red[tid] += red[tid + o];
        __syncthreads();
    }
    const float wsum = red[0];
    if (tid < 128) wk[tid] = (myw / wsum) * kf;
    __syncthreads();

    float acc = 0.f;
    if (tid < 128) {
        for (int t = 0; t < TT; t++)
            acc += wk[t] * g_ys_f[((ll)t * BB + b) * HH + tid];
    } else {
        const int k = tid - 128;
        for (int t = 0; t < TT; t++)
            acc += wk[t] * g_ys_b[((ll)(TT - 1 - t) * BB + b) * HH + k];
    }
    out[b * DD + tid] = acc;

    float* hout = out + BB * DD;
    if (tid < 128) {
        hout[b * HH + tid] = g_ys_f[((ll)(TT - 1) * BB + b) * HH + tid];
    } else {
        const int k = tid - 128;
        hout[BB * HH + b * HH + k] = g_ys_b[((ll)(TT - 1) * BB + b) * HH + k];
    }
}

// ============================================================
extern "C" void kernel_launch(void* const* d_in, const int* in_sizes, int n_in,
                              void* d_out, int out_size)
{
    const int*   tokens = (const int*)d_in[0];
    const float* hidden = (const float*)d_in[1];
    const float* emb    = (const float*)d_in[2];
    const float* W_ih_f = (const float*)d_in[3];
    const float* W_hh_f = (const float*)d_in[4];
    const float* b_ih_f = (const float*)d_in[5];
    const float* b_hh_f = (const float*)d_in[6];
    const float* W_ih_b = (const float*)d_in[7];
    const float* W_hh_b = (const float*)d_in[8];
    const float* b_ih_b = (const float*)d_in[9];
    const float* b_hh_b = (const float*)d_in[10];
    const float* attn2W = (const float*)d_in[11];
    const float* attn2b = (const float*)d_in[12];
    const float* cent   = (const float*)d_in[13];
    const float* beta   = (const float*)d_in[14];
    float* out = (float*)d_out;

    cudaFuncSetAttribute(k1_mma, cudaFuncAttributeMaxDynamicSharedMemorySize, K1_SMEM);
    cudaFuncSetAttribute(k2_mma, cudaFuncAttributeMaxDynamicSharedMemorySize, K2_SMEM);
    cudaFuncSetAttribute(k3_mma, cudaFuncAttributeMaxDynamicSharedMemorySize, MMA_SMEM);

    // k0 x3 so the ncu capture slot (4th launch) = k1_mma
    k0_cent<<<1, 32>>>(cent);
    k0_cent<<<1, 32>>>(cent);
    k0_cent<<<1, 32>>>(cent);
    k1_mma<<<dim3(6, 512), 256, K1_SMEM>>>(tokens, emb, W_ih_f, b_ih_f, W_ih_b, b_ih_b);
    k2_mma<<<128, 256, K2_SMEM>>>(hidden, W_hh_f, b_hh_f, W_hh_b, b_hh_b);
    k3_mma<<<dim3(2, 512), 256, MMA_SMEM>>>(attn2W, attn2b);
    k34_scores<<<8192, 256>>>(cent, beta);
    k5_pool<<<512, 256>>>(out);
}

// round 15
// speedup vs baseline: 1.3925x; 1.0074x over previous
#include <cuda_runtime.h>
#include <math.h>

#define TT   128
#define BB   512
#define HH   128
#define EMBD 300
#define DD   256
#define G3   384
#define EPSF 1e-7f

typedef long long ll;

__device__ float g_xp_f[TT * BB * G3];
__device__ float g_xp_b[TT * BB * G3];
__device__ float g_ys_f[TT * BB * HH];
__device__ float g_ys_b[TT * BB * HH];
__device__ float g_hyp[TT * BB * DD];
__device__ float g_scores[TT * BB];
__device__ float g_rr2[TT * BB];
__device__ float g_cc[2];   // [cosh(rc), sinh(rc)/rc]

// ---- tf32 helpers ----
__device__ __forceinline__ unsigned f2tf32(float v) {      // RNA
    unsigned u;
    asm("cvt.rna.tf32.f32 %0, %1;" : "=r"(u) : "f"(v));
    return u;
}
__device__ __forceinline__ void mma_tf32(float* c, const unsigned* a, const unsigned* b) {
    asm volatile(
        "mma.sync.aligned.m16n8k8.row.col.f32.tf32.tf32.f32 "
        "{%0,%1,%2,%3}, {%4,%5,%6,%7}, {%8,%9}, {%0,%1,%2,%3};"
        : "+f"(c[0]), "+f"(c[1]), "+f"(c[2]), "+f"(c[3])
        : "r"(a[0]), "r"(a[1]), "r"(a[2]), "r"(a[3]), "r"(b[0]), "r"(b[1]));
}

__device__ __forceinline__ void cpa16(float* dst_smem, const void* src, bool valid) {
    unsigned d = (unsigned)__cvta_generic_to_shared(dst_smem);
    int sz = valid ? 16 : 0;          // src-size 0 => 16B zero-fill
    asm volatile("cp.async.cg.shared.global [%0], [%1], 16, %2;"
                 :: "r"(d), "l"(src), "r"(sz) : "memory");
}

// ---- K3 fragment-major layout ----
#define ACH 1032
#define BCH 1032
#define MMA_SMEM ((8 * ACH + 8 * BCH) * 4)   // 66,048 B

__device__ __forceinline__ int a_off(int r, int kk) {
    return (kk >> 3) * ACH + (r >> 4) * 128 + ((((r & 7) << 2) | (kk & 3)) << 2)
           + ((r >> 3) & 1) + (((kk >> 2) & 1) << 1);
}
__device__ __forceinline__ int b_off(int c, int kk) {
    return (kk >> 3) * BCH + (c >> 3) * 64 + ((((c & 7) << 2) | (kk & 3)) << 1)
           + ((kk >> 2) & 1);
}

// K1: 4-stage ring, K=16 slices: 4 x (A 2048 + B 2048) floats = 65,536 B
#define K1_SMEM (4 * 4096 * 4)
#define K1_NS 19                     // 19 * 16 = 304 >= 300

// K2 smem: B-frags ktiles 6..15 (10 kt) + double-buffered h_A
#define K2_SMEM (122880 + 16384)     // 139,264 B

// ============================================================
// K0: centroid constants — idempotent
// ============================================================
__global__ void k0_cent(const float* __restrict__ cent)
{
    const int lane = threadIdx.x;
    float c2 = 0.f;
    #pragma unroll
    for (int i = 0; i < 8; i++) {
        const float cv = cent[lane + 32 * i];
        c2 += cv * cv;
    }
    #pragma unroll
    for (int o = 16; o; o >>= 1) c2 += __shfl_xor_sync(0xffffffffu, c2, o);
    if (lane == 0) {
        const float rc = sqrtf(c2);
        g_cc[0] = coshf(rc);
        g_cc[1] = sinhf(rc) / rc;
    }
}

// ============================================================
// K1: embed gather + input projections via tf32 mma.
// 4-deep cp.async ring, K=16 slices, one sync per slice.
// ============================================================
__global__ __launch_bounds__(256, 2) void k1_mma(
    const int* __restrict__ tokens, const float* __restrict__ emb,
    const float* __restrict__ Wf, const float* __restrict__ bfv,
    const float* __restrict__ Wb, const float* __restrict__ bbv)
{
    extern __shared__ float smf[];
    __shared__ int tk[128];

    const int tid  = threadIdx.x;
    const int lane = tid & 31;
    const int w    = tid >> 5;
    const int wm   = w >> 2;            // 0..1 : 64 rows
    const int wn   = w & 3;             // 0..3 : 32 cols
    const int row0 = blockIdx.y * 128;
    const int t    = row0 >> 9;
    const int b0   = row0 & 511;
    const int coff = blockIdx.x * 128;

    const bool fwd = (coff < G3);
    const float* Wsrc = fwd ? Wf : Wb;
    const float* bsrc = fwd ? bfv : bbv;
    const int cbase = fwd ? coff : (coff - G3);

    if (tid < 128) tk[tid] = tokens[row0 + tid];
    __syncthreads();

    const int fl    = tid & 3;          // 16B chunk along k16 slice
    const int rr    = tid >> 2;         // 0..63 rows/cols per pass
    const int ktile = fl >> 1;          // 0..1
    const int khalf = fl & 1;

    auto stage = [&](int s) {
        float* A = smf + (s & 3) * 4096;
        float* B = A + 2048;
        const int kg4 = s * 16 + fl * 4;
        const bool kv = (kg4 < EMBD);   // EMBD%4==0 -> all-or-nothing
        #pragma unroll
        for (int rp = 0; rp < 2; rp++) {
            const int r = rp * 64 + rr;
            const int areg = ((r & 15) >> 3) + khalf * 2;
            cpa16(A + ktile * 1024 + (r >> 4) * 128 + areg * 32 + (r & 7) * 4,
                  emb + (ll)tk[r] * EMBD + kg4, kv);
            const int c = rp * 64 + rr;
            cpa16(B + ktile * 1024 + (c >> 3) * 64 + khalf * 32 + (c & 7) * 4,
                  Wsrc + (ll)(cbase + c) * EMBD + kg4, kv);
        }
        asm volatile("cp.async.commit_group;" ::: "memory");
    };

    float acc[4][4][4];
    #pragma unroll
    for (int i = 0; i < 4; i++)
        #pragma unroll
        for (int j = 0; j < 4; j++)
            #pragma unroll
            for (int q = 0; q < 4; q++) acc[i][j][q] = 0.f;

    stage(0); stage(1); stage(2);

    for (int s = 0; s < K1_NS; s++) {
        // wait until group s complete (conservative at the tail)
        if (s + 3 < K1_NS)      asm volatile("cp.async.wait_group 2;" ::: "memory");
        else if (s + 2 < K1_NS) asm volatile("cp.async.wait_group 1;" ::: "memory");
        else                    asm volatile("cp.async.wait_group 0;" ::: "memory");
        __syncthreads();                 // all warps done reading buf (s-1)&3
        if (s + 3 < K1_NS) stage(s + 3); // overwrites buf (s-1)&3 — safe now

        const unsigned* Au = (const unsigned*)(smf + (s & 3) * 4096);
        const unsigned* Bu = Au + 2048;

        #pragma unroll
        for (int ck = 0; ck < 2; ck++) {
            unsigned a[4][4], b[4][2];
            #pragma unroll
            for (int i = 0; i < 4; i++) {
                const unsigned* ap = Au + ck * 1024 + (wm * 4 + i) * 128 + lane;
                a[i][0] = ap[0]; a[i][1] = ap[32]; a[i][2] = ap[64]; a[i][3] = ap[96];
            }
            #pragma unroll
            for (int j = 0; j < 4; j++) {
                const unsigned* bp = Bu + ck * 1024 + (wn * 4 + j) * 64 + lane;
                b[j][0] = bp[0]; b[j][1] = bp[32];
            }
            #pragma unroll
            for (int i = 0; i < 4; i++)
                #pragma unroll
                for (int j = 0; j < 4; j++)
                    mma_tf32(acc[i][j], a[i], b[j]);
        }
    }

    const int tb = TT - 1 - t;
    #pragma unroll
    for (int j = 0; j < 4; j++) {
        const int cl = cbase + wn * 32 + j * 8 + 2 * (lane & 3);
        const float bv0 = bsrc[cl], bv1 = bsrc[cl + 1];
        #pragma unroll
        for (int i = 0; i < 4; i++) {
            const int b_lo = b0 + wm * 64 + i * 16 + (lane >> 2);
            float2 vlo = make_float2(acc[i][j][0] + bv0, acc[i][j][1] + bv1);
            float2 vhi = make_float2(acc[i][j][2] + bv0, acc[i][j][3] + bv1);
            if (fwd) {
                *(float2*)&g_xp_f[((ll)t * BB + b_lo) * G3 + cl] = vlo;
                *(float2*)&g_xp_f[((ll)t * BB + b_lo + 8) * G3 + cl] = vhi;
            } else {
                *(float2*)&g_xp_b[((ll)tb * BB + b_lo) * G3 + cl] = vlo;
                *(float2*)&g_xp_b[((ll)tb * BB + b_lo + 8) * G3 + cl] = vhi;
            }
        }
    }
}

// ============================================================
// K2: GRU scan via tf32 MMA (R13 form).
// ============================================================
__global__ __launch_bounds__(256, 1) void k2_mma(
    const float* __restrict__ hidden,
    const float* __restrict__ Whh_f, const float* __restrict__ bhh_f,
    const float* __restrict__ Whh_b, const float* __restrict__ bhh_b)
{
    extern __shared__ float smf[];
    float* sB = smf;              // [w][kt-6 (10)][nt (6)][lane][2]
    float* hA = smf + 30720;      // 2 x 2048 floats

    const int tid  = threadIdx.x;
    const int lane = tid & 31;
    const int w    = tid >> 5;
    const int dir  = blockIdx.x >> 6;
    const int b0   = (blockIdx.x & 63) * 8;

    const float* Whh = dir ? Whh_b : Whh_f;
    const float* bhh = dir ? bhh_b : bhh_f;
    const float* xp  = dir ? g_xp_b : g_xp_f;
    float* ys        = dir ? g_ys_b : g_ys_f;

    const int m  = lane >> 2;
    const int q  = lane & 3;
    const int ks = w * 16;

    int gbase[6];
    gbase[0] = ks;       gbase[1] = ks + 8;
    gbase[2] = 128 + ks; gbase[3] = 128 + ks + 8;
    gbase[4] = 256 + ks; gbase[5] = 256 + ks + 8;

    unsigned breg[6][6][2];
    #pragma unroll
    for (int kt = 0; kt < 6; kt++)
        #pragma unroll
        for (int nt = 0; nt < 6; nt++) {
            const float* wr = Whh + (ll)(gbase[nt] + m) * HH + kt * 8 + q;
            breg[kt][nt][0] = f2tf32(wr[0]);
            breg[kt][nt][1] = f2tf32(wr[4]);
        }
    #pragma unroll
    for (int kt = 6; kt < 16; kt++)
        #pragma unroll
        for (int nt = 0; nt < 6; nt++) {
            const float* wr = Whh + (ll)(gbase[nt] + m) * HH + kt * 8 + q;
            float* d = sB + (((w * 10 + (kt - 6)) * 6 + nt) * 32 + lane) * 2;
            d[0] = __uint_as_float(f2tf32(wr[0]));
            d[1] = __uint_as_float(f2tf32(wr[4]));
        }

    float bh[3][4];
    #pragma unroll
    for (int g = 0; g < 3; g++)
        #pragma unroll
        for (int p = 0; p < 2; p++) {
            const float2 v = *(const float2*)(bhh + g * 128 + ks + p * 8 + q * 2);
            bh[g][p * 2 + 0] = v.x;
            bh[g][p * 2 + 1] = v.y;
        }

    for (int i = tid; i < 4096; i += 256) hA[i] = 0.f;
    __syncthreads();

    float hold[4];
    #pragma unroll
    for (int p = 0; p < 2; p++) {
        const float2 v = *(const float2*)(hidden + ((ll)dir * BB + b0 + m) * HH + ks + p * 8 + q * 2);
        hold[p * 2 + 0] = v.x;
        hold[p * 2 + 1] = v.y;
        #pragma unroll
        for (int d_ = 0; d_ < 2; d_++) {
            const int k = ks + p * 8 + q * 2 + d_;
            hA[(k >> 3) * 128 + ((m << 2) | (k & 3)) * 4 + ((k & 4) ? 2 : 0)]
                = __uint_as_float(f2tf32(hold[p * 2 + d_]));
        }
    }
    __syncthreads();

    float xv[3][4], xvn[3][4];
    #pragma unroll
    for (int g = 0; g < 3; g++)
        #pragma unroll
        for (int p = 0; p < 2; p++) {
            const float2 v = *(const float2*)(xp + ((ll)(b0 + m)) * G3 + g * 128 + ks + p * 8 + q * 2);
            xv[g][p * 2 + 0] = v.x;
            xv[g][p * 2 + 1] = v.y;
        }

    for (int t = 0; t < TT; t++) {
        const float* hAc = hA + (t & 1) * 2048;
        float* hAn       = hA + ((t + 1) & 1) * 2048;

        const int tn = (t + 1 < TT) ? (t + 1) : t;
        #pragma unroll
        for (int g = 0; g < 3; g++)
            #pragma unroll
            for (int p = 0; p < 2; p++) {
                const float2 v = *(const float2*)(xp + ((ll)tn * BB + b0 + m) * G3 + g * 128 + ks + p * 8 + q * 2);
                xvn[g][p * 2 + 0] = v.x;
                xvn[g][p * 2 + 1] = v.y;
            }

        float acc0[6][4], acc1[6][4];
        #pragma unroll
        for (int nt = 0; nt < 6; nt++)
            #pragma unroll
            for (int c = 0; c < 4; c++) { acc0[nt][c] = 0.f; acc1[nt][c] = 0.f; }

        #pragma unroll
        for (int kt = 0; kt < 16; kt++) {
            uint4 av = *(const uint4*)(hAc + kt * 128 + lane * 4);
            unsigned a[4] = {av.x, av.y, av.z, av.w};
            if (kt < 6) {
                #pragma unroll
                for (int nt = 0; nt < 6; nt++)
                    mma_tf32(acc0[nt], a, breg[kt][nt]);
            } else {
                #pragma unroll
                for (int nt = 0; nt < 6; nt++) {
                    const float2 bv = *(const float2*)(sB + (((w * 10 + (kt - 6)) * 6 + nt) * 32 + lane) * 2);
                    unsigned b[2] = {__float_as_uint(bv.x), __float_as_uint(bv.y)};
                    mma_tf32(acc1[nt], a, b);
                }
            }
        }

        float hnew[4];
        #pragma unroll
        for (int p = 0; p < 2; p++)
            #pragma unroll
            for (int d_ = 0; d_ < 2; d_++) {
                const int i = p * 2 + d_;
                const float hr = acc0[p][d_] + acc1[p][d_];
                const float hz = acc0[2 + p][d_] + acc1[2 + p][d_];
                const float hn = acc0[4 + p][d_] + acc1[4 + p][d_];
                const float rs = xv[0][i] + hr + bh[0][i];
                const float zs = xv[1][i] + hz + bh[1][i];
                const float rg = __fdividef(1.f, 1.f + __expf(-rs));
                const float zg = __fdividef(1.f, 1.f + __expf(-zs));
                const float a_ = xv[2][i] + rg * (hn + bh[2][i]);
                const float e  = __expf(2.f * a_);
                const float n_ = 1.f - __fdividef(2.f, e + 1.f);
                hnew[i] = (1.f - zg) * n_ + zg * hold[i];
                hold[i] = hnew[i];
                const int k = ks + p * 8 + q * 2 + d_;
                hAn[(k >> 3) * 128 + ((m << 2) | (k & 3)) * 4 + ((k & 4) ? 2 : 0)]
                    = __uint_as_float(f2tf32(hnew[i]));
            }

        #pragma unroll
        for (int p = 0; p < 2; p++)
            *(float2*)(ys + ((ll)t * BB + b0 + m) * HH + ks + p * 8 + q * 2)
                = make_float2(hnew[p * 2], hnew[p * 2 + 1]);

        #pragma unroll
        for (int g = 0; g < 3; g++)
            #pragma unroll
            for (int i = 0; i < 4; i++) xv[g][i] = xvn[g][i];

        __syncthreads();
    }
}

// ============================================================
// K3: hyp = tanh(f @ attn2_W^T + b) via tf32 mma (RNA, R8 form)
// ============================================================
__global__ __launch_bounds__(256) void k3_mma(
    const float* __restrict__ W, const float* __restrict__ bias)
{
    extern __shared__ float smf[];
    unsigned* As = (unsigned*)smf;
    unsigned* Bs = As + 8 * ACH;

    const int tid  = threadIdx.x;
    const int lane = tid & 31;
    const int w    = tid >> 5;
    const int wm   = w >> 2;
    const int wn   = w & 3;
    const int row0 = blockIdx.y * 128;
    const int t    = row0 >> 9;
    const int b0   = row0 & 511;
    const int tb   = TT - 1 - t;
    const int coff = blockIdx.x * 128;

    float acc[4][4][4];
    #pragma unroll
    for (int i = 0; i < 4; i++)
        #pragma unroll
        for (int j = 0; j < 4; j++)
            #pragma unroll
            for (int q = 0; q < 4; q++) acc[i][j][q] = 0.f;

    const int fl = tid & 15;
    const int rr = tid >> 4;

    for (int ks = 0; ks < 4; ks++) {
        const int kg4 = ks * 64 + fl * 4;
        __syncthreads();
        const float* ysrc = (ks < 2) ? (g_ys_f + (ll)t * BB * HH)
                                     : (g_ys_b + (ll)tb * BB * HH);
        const int kk4 = (ks < 2) ? kg4 : (kg4 - HH);
        #pragma unroll
        for (int rp = 0; rp < 8; rp++) {
            const int r = rp * 16 + rr;
            float4 v = *(const float4*)(ysrc + (ll)(b0 + r) * HH + kk4);
            As[a_off(r, fl * 4 + 0)] = f2tf32(v.x);
            As[a_off(r, fl * 4 + 1)] = f2tf32(v.y);
            As[a_off(r, fl * 4 + 2)] = f2tf32(v.z);
            As[a_off(r, fl * 4 + 3)] = f2tf32(v.w);
        }
        #pragma unroll
        for (int cp = 0; cp < 8; cp++) {
            const int c = cp * 16 + rr;
            float4 v = *(const float4*)(W + (ll)(coff + c) * DD + kg4);
            Bs[b_off(c, fl * 4 + 0)] = f2tf32(v.x);
            Bs[b_off(c, fl * 4 + 1)] = f2tf32(v.y);
            Bs[b_off(c, fl * 4 + 2)] = f2tf32(v.z);
            Bs[b_off(c, fl * 4 + 3)] = f2tf32(v.w);
        }
        __syncthreads();
        #pragma unroll
        for (int ck = 0; ck < 8; ck++) {
            unsigned a[4][4], b[4][2];
            #pragma unroll
            for (int i = 0; i < 4; i++) {
                uint4 av = *(const uint4*)(As + ck * ACH + (wm * 4 + i) * 128 + lane * 4);
                a[i][0] = av.x; a[i][1] = av.y; a[i][2] = av.z; a[i][3] = av.w;
            }
            #pragma unroll
            for (int j = 0; j < 4; j++) {
                uint2 bv = *(const uint2*)(Bs + ck * BCH + (wn * 4 + j) * 64 + lane * 2);
                b[j][0] = bv.x; b[j][1] = bv.y;
            }
            #pragma unroll
            for (int i = 0; i < 4; i++)
                #pragma unroll
                for (int j = 0; j < 4; j++)
                    mma_tf32(acc[i][j], a[i], b[j]);
        }
    }

    #pragma unroll
    for (int j = 0; j < 4; j++) {
        const int n = coff + wn * 32 + j * 8 + 2 * (lane & 3);
        const float bv0 = bias[n], bv1 = bias[n + 1];
        #pragma unroll
        for (int i = 0; i < 4; i++) {
            const int m_lo = row0 + wm * 64 + i * 16 + (lane >> 2);
            float v[4] = {acc[i][j][0] + bv0, acc[i][j][1] + bv1,
                          acc[i][j][2] + bv0, acc[i][j][3] + bv1};
            #pragma unroll
            for (int qq = 0; qq < 4; qq++) {
                const float e = __expf(2.f * v[qq]);
                v[qq] = 1.f - __fdividef(2.f, e + 1.f);
            }
            *(float2*)&g_hyp[(ll)m_lo * DD + n] = make_float2(v[0], v[1]);
            *(float2*)&g_hyp[(ll)(m_lo + 8) * DD + n] = make_float2(v[2], v[3]);
        }
    }
}

// ============================================================
// K34: fused ||f||^2 + hyperbolic score, one warp per (t,b) row
// ============================================================
__global__ __launch_bounds__(256) void k34_scores(
    const float* __restrict__ cent, const float* __restrict__ beta)
{
    const int row  = blockIdx.x * 8 + (threadIdx.x >> 5);
    const int lane = threadIdx.x & 31;
    const int t = row >> 9, b = row & 511;
    const float* yf = g_ys_f + ((ll)t * BB + b) * HH;
    const float* yb = g_ys_b + ((ll)(TT - 1 - t) * BB + b) * HH;
    const float* hy = g_hyp + (ll)row * DD;

    float s = 0.f, h2 = 0.f, cd = 0.f;
    #pragma unroll
    for (int i = 0; i < 4; i++) {
        const float a = yf[lane + 32 * i];
        const float c = yb[lane + 32 * i];
        s += a * a + c * c;
    }
    #pragma unroll
    for (int i = 0; i < 8; i++) {
        const float hv = hy[lane + 32 * i];
        const float cv = cent[lane + 32 * i];
        h2 += hv * hv; cd += hv * cv;
    }
    #pragma unroll
    for (int o = 16; o; o >>= 1) {
        s  += __shfl_xor_sync(0xffffffffu, s, o);
        h2 += __shfl_xor_sync(0xffffffffu, h2, o);
        cd += __shfl_xor_sync(0xffffffffu, cd, o);
    }
    if (lane == 0) {
        g_rr2[row] = s;
        const float rh = sqrtf(h2);
        float pm = coshf(rh) * g_cc[0] - (sinhf(rh) / rh) * g_cc[1] * cd;
        pm = fminf(fmaxf(pm, 1.f + EPSF), 1e16f);
        const float dist = logf(pm) + log1pf(sqrtf(pm * pm - 1.f + EPSF) / pm);
        g_scores[row] = -beta[0] * dist - 1.f;
    }
}

// ============================================================
// K5: softmax x gamma Einstein-midpoint pooling + h_output
// ============================================================
__global__ __launch_bounds__(256) void k5_pool(float* __restrict__ out)
{
    __shared__ float wk[128];
    __shared__ float red[128];
    const int b = blockIdx.x, tid = threadIdx.x;

    float s = -1e30f;
    if (tid < 128) {
        s = g_scores[tid * BB + b];
        red[tid] = s;
    }
    __syncthreads();
    for (int o = 64; o; o >>= 1) {
        if (tid < o) red[tid] = fmaxf(red[tid], red[tid + o]);
        __syncthreads();
    }
    const float smax = red[0];
    __syncthreads();

    float myw = 0.f, kf = 0.f;
    if (tid < 128) {
        const float rr = sqrtf(g_rr2[tid * BB + b]);
        const float sh = sinhf(rr), ch = coshf(rr);
        const float th = sh / ch;
        float gsq = 1.f - th * th;
        gsq = fminf(fmaxf(gsq, EPSF), 1.f - EPSF);
        float gam = 1.f / sqrtf(gsq);
        gam = fminf(fmaxf(gam, 1.f + EPSF), 1e16f);
        myw = __expf(s - smax) * gam;
        kf = th / rr;
        red[tid] = myw;
    }
    __syncthreads();
    for (int o = 64; o; o >>= 1) {
        if (tid < o) red[tid] += red[tid + o];
        __syncthreads();
    }
    const float wsum = red[0];
    if (tid < 128) wk[tid] = (myw / wsum) * kf;
    __syncthreads();

    float acc = 0.f;
    if (tid < 128) {
        for (int t = 0; t < TT; t++)
            acc += wk[t] * g_ys_f[((ll)t * BB + b) * HH + tid];
    } else {
        const int k = tid - 128;
        for (int t = 0; t < TT; t++)
            acc += wk[t] * g_ys_b[((ll)(TT - 1 - t) * BB + b) * HH + k];
    }
    out[b * DD + tid] = acc;

    float* hout = out + BB * DD;
    if (tid < 128) {
        hout[b * HH + tid] = g_ys_f[((ll)(TT - 1) * BB + b) * HH + tid];
    } else {
        const int k = tid - 128;
        hout[BB * HH + b * HH + k] = g_ys_b[((ll)(TT - 1) * BB + b) * HH + k];
    }
}

// ============================================================
extern "C" void kernel_launch(void* const* d_in, const int* in_sizes, int n_in,
                              void* d_out, int out_size)
{
    const int*   tokens = (const int*)d_in[0];
    const float* hidden = (const float*)d_in[1];
    const float* emb    = (const float*)d_in[2];
    const float* W_ih_f = (const float*)d_in[3];
    const float* W_hh_f = (const float*)d_in[4];
    const float* b_ih_f = (const float*)d_in[5];
    const float* b_hh_f = (const float*)d_in[6];
    const float* W_ih_b = (const float*)d_in[7];
    const float* W_hh_b = (const float*)d_in[8];
    const float* b_ih_b = (const float*)d_in[9];
    const float* b_hh_b = (const float*)d_in[10];
    const float* attn2W = (const float*)d_in[11];
    const float* attn2b = (const float*)d_in[12];
    const float* cent   = (const float*)d_in[13];
    const float* beta   = (const float*)d_in[14];
    float* out = (float*)d_out;

    cudaFuncSetAttribute(k1_mma, cudaFuncAttributeMaxDynamicSharedMemorySize, K1_SMEM);
    cudaFuncSetAttribute(k2_mma, cudaFuncAttributeMaxDynamicSharedMemorySize, K2_SMEM);
    cudaFuncSetAttribute(k3_mma, cudaFuncAttributeMaxDynamicSharedMemorySize, MMA_SMEM);

    // k0 x3 so the ncu capture slot (4th launch) = k1_mma
    k0_cent<<<1, 32>>>(cent);
    k0_cent<<<1, 32>>>(cent);
    k0_cent<<<1, 32>>>(cent);
    k1_mma<<<dim3(6, 512), 256, K1_SMEM>>>(tokens, emb, W_ih_f, b_ih_f, W_ih_b, b_ih_b);
    k2_mma<<<128, 256, K2_SMEM>>>(hidden, W_hh_f, b_hh_f, W_hh_b, b_hh_b);
    k3_mma<<<dim3(2, 512), 256, MMA_SMEM>>>(attn2W, attn2b);
    k34_scores<<<8192, 256>>>(cent, beta);
    k5_pool<<<512, 256>>>(out);
}

// round 16
// speedup vs baseline: 1.4785x; 1.0617x over previous
#include <cuda_runtime.h>
#include <math.h>

#define TT   128
#define BB   512
#define HH   128
#define EMBD 300
#define DD   256
#define G3   384
#define EPSF 1e-7f

typedef long long ll;

__device__ float g_xp_f[TT * BB * G3];
__device__ float g_xp_b[TT * BB * G3];
__device__ float g_ys_f[TT * BB * HH];
__device__ float g_ys_b[TT * BB * HH];
__device__ float g_scores[TT * BB];
__device__ float g_rr2[TT * BB];
__device__ float g_cc[2];   // [cosh(rc), sinh(rc)/rc]

// ---- tf32 helpers ----
__device__ __forceinline__ unsigned f2tf32(float v) {      // RNA
    unsigned u;
    asm("cvt.rna.tf32.f32 %0, %1;" : "=r"(u) : "f"(v));
    return u;
}
__device__ __forceinline__ void mma_tf32(float* c, const unsigned* a, const unsigned* b) {
    asm volatile(
        "mma.sync.aligned.m16n8k8.row.col.f32.tf32.tf32.f32 "
        "{%0,%1,%2,%3}, {%4,%5,%6,%7}, {%8,%9}, {%0,%1,%2,%3};"
        : "+f"(c[0]), "+f"(c[1]), "+f"(c[2]), "+f"(c[3])
        : "r"(a[0]), "r"(a[1]), "r"(a[2]), "r"(a[3]), "r"(b[0]), "r"(b[1]));
}

__device__ __forceinline__ void cpa16(float* dst_smem, const void* src, bool valid) {
    unsigned d = (unsigned)__cvta_generic_to_shared(dst_smem);
    int sz = valid ? 16 : 0;          // src-size 0 => 16B zero-fill
    asm volatile("cp.async.cg.shared.global [%0], [%1], 16, %2;"
                 :: "r"(d), "l"(src), "r"(sz) : "memory");
}

// ---- fragment-major layouts ----
#define ACH 1032
#define BCH2 2056                     // 256-col B tile per kk-row (+8 pad)

__device__ __forceinline__ int a_off(int r, int kk) {
    return (kk >> 3) * ACH + (r >> 4) * 128 + ((((r & 7) << 2) | (kk & 3)) << 2)
           + ((r >> 3) & 1) + (((kk >> 2) & 1) << 1);
}
__device__ __forceinline__ int b_off2(int c, int kk) {
    return (kk >> 3) * BCH2 + (c >> 3) * 64 + ((((c & 7) << 2) | (kk & 3)) << 1)
           + ((kk >> 2) & 1);
}

// K1: 4-stage ring, K=16 slices: 4 x (A 2048 + B 2048) floats = 65,536 B
#define K1_SMEM (4 * 4096 * 4)
#define K1_NS 19

// K2 smem
#define K2_SMEM (122880 + 16384)

// K3v2 smem: As 8*ACH + Bs 8*BCH2 + sh2 1024 + scd 1024 + srr 128 + scent 256 + sbias 256
#define K3V2_U32 (8 * ACH + 8 * BCH2)
#define K3V2_SMEM ((K3V2_U32 + 1024 + 1024 + 128 + 256 + 256) * 4)   // 109,568 B

// ============================================================
// K0: centroid constants
// ============================================================
__global__ void k0_cent(const float* __restrict__ cent)
{
    const int lane = threadIdx.x;
    float c2 = 0.f;
    #pragma unroll
    for (int i = 0; i < 8; i++) {
        const float cv = cent[lane + 32 * i];
        c2 += cv * cv;
    }
    #pragma unroll
    for (int o = 16; o; o >>= 1) c2 += __shfl_xor_sync(0xffffffffu, c2, o);
    if (lane == 0) {
        const float rc = sqrtf(c2);
        g_cc[0] = coshf(rc);
        g_cc[1] = sinhf(rc) / rc;
    }
}

// ============================================================
// K1: embed gather + input projections (R15 form, unchanged)
// ============================================================
__global__ __launch_bounds__(256, 2) void k1_mma(
    const int* __restrict__ tokens, const float* __restrict__ emb,
    const float* __restrict__ Wf, const float* __restrict__ bfv,
    const float* __restrict__ Wb, const float* __restrict__ bbv)
{
    extern __shared__ float smf[];
    __shared__ int tk[128];

    const int tid  = threadIdx.x;
    const int lane = tid & 31;
    const int w    = tid >> 5;
    const int wm   = w >> 2;
    const int wn   = w & 3;
    const int row0 = blockIdx.y * 128;
    const int t    = row0 >> 9;
    const int b0   = row0 & 511;
    const int coff = blockIdx.x * 128;

    const bool fwd = (coff < G3);
    const float* Wsrc = fwd ? Wf : Wb;
    const float* bsrc = fwd ? bfv : bbv;
    const int cbase = fwd ? coff : (coff - G3);

    if (tid < 128) tk[tid] = tokens[row0 + tid];
    __syncthreads();

    const int fl    = tid & 3;
    const int rr    = tid >> 2;
    const int ktile = fl >> 1;
    const int khalf = fl & 1;

    auto stage = [&](int s) {
        float* A = smf + (s & 3) * 4096;
        float* B = A + 2048;
        const int kg4 = s * 16 + fl * 4;
        const bool kv = (kg4 < EMBD);
        #pragma unroll
        for (int rp = 0; rp < 2; rp++) {
            const int r = rp * 64 + rr;
            const int areg = ((r & 15) >> 3) + khalf * 2;
            cpa16(A + ktile * 1024 + (r >> 4) * 128 + areg * 32 + (r & 7) * 4,
                  emb + (ll)tk[r] * EMBD + kg4, kv);
            const int c = rp * 64 + rr;
            cpa16(B + ktile * 1024 + (c >> 3) * 64 + khalf * 32 + (c & 7) * 4,
                  Wsrc + (ll)(cbase + c) * EMBD + kg4, kv);
        }
        asm volatile("cp.async.commit_group;" ::: "memory");
    };

    float acc[4][4][4];
    #pragma unroll
    for (int i = 0; i < 4; i++)
        #pragma unroll
        for (int j = 0; j < 4; j++)
            #pragma unroll
            for (int q = 0; q < 4; q++) acc[i][j][q] = 0.f;

    stage(0); stage(1); stage(2);

    for (int s = 0; s < K1_NS; s++) {
        if (s + 3 < K1_NS)      asm volatile("cp.async.wait_group 2;" ::: "memory");
        else if (s + 2 < K1_NS) asm volatile("cp.async.wait_group 1;" ::: "memory");
        else                    asm volatile("cp.async.wait_group 0;" ::: "memory");
        __syncthreads();
        if (s + 3 < K1_NS) stage(s + 3);

        const unsigned* Au = (const unsigned*)(smf + (s & 3) * 4096);
        const unsigned* Bu = Au + 2048;

        #pragma unroll
        for (int ck = 0; ck < 2; ck++) {
            unsigned a[4][4], b[4][2];
            #pragma unroll
            for (int i = 0; i < 4; i++) {
                const unsigned* ap = Au + ck * 1024 + (wm * 4 + i) * 128 + lane;
                a[i][0] = ap[0]; a[i][1] = ap[32]; a[i][2] = ap[64]; a[i][3] = ap[96];
            }
            #pragma unroll
            for (int j = 0; j < 4; j++) {
                const unsigned* bp = Bu + ck * 1024 + (wn * 4 + j) * 64 + lane;
                b[j][0] = bp[0]; b[j][1] = bp[32];
            }
            #pragma unroll
            for (int i = 0; i < 4; i++)
                #pragma unroll
                for (int j = 0; j < 4; j++)
                    mma_tf32(acc[i][j], a[i], b[j]);
        }
    }

    const int tb = TT - 1 - t;
    #pragma unroll
    for (int j = 0; j < 4; j++) {
        const int cl = cbase + wn * 32 + j * 8 + 2 * (lane & 3);
        const float bv0 = bsrc[cl], bv1 = bsrc[cl + 1];
        #pragma unroll
        for (int i = 0; i < 4; i++) {
            const int b_lo = b0 + wm * 64 + i * 16 + (lane >> 2);
            float2 vlo = make_float2(acc[i][j][0] + bv0, acc[i][j][1] + bv1);
            float2 vhi = make_float2(acc[i][j][2] + bv0, acc[i][j][3] + bv1);
            if (fwd) {
                *(float2*)&g_xp_f[((ll)t * BB + b_lo) * G3 + cl] = vlo;
                *(float2*)&g_xp_f[((ll)t * BB + b_lo + 8) * G3 + cl] = vhi;
            } else {
                *(float2*)&g_xp_b[((ll)tb * BB + b_lo) * G3 + cl] = vlo;
                *(float2*)&g_xp_b[((ll)tb * BB + b_lo + 8) * G3 + cl] = vhi;
            }
        }
    }
}

// ============================================================
// K2: GRU scan via tf32 MMA (R13/R15 form, unchanged)
// ============================================================
__global__ __launch_bounds__(256, 1) void k2_mma(
    const float* __restrict__ hidden,
    const float* __restrict__ Whh_f, const float* __restrict__ bhh_f,
    const float* __restrict__ Whh_b, const float* __restrict__ bhh_b)
{
    extern __shared__ float smf[];
    float* sB = smf;
    float* hA = smf + 30720;

    const int tid  = threadIdx.x;
    const int lane = tid & 31;
    const int w    = tid >> 5;
    const int dir  = blockIdx.x >> 6;
    const int b0   = (blockIdx.x & 63) * 8;

    const float* Whh = dir ? Whh_b : Whh_f;
    const float* bhh = dir ? bhh_b : bhh_f;
    const float* xp  = dir ? g_xp_b : g_xp_f;
    float* ys        = dir ? g_ys_b : g_ys_f;

    const int m  = lane >> 2;
    const int q  = lane & 3;
    const int ks = w * 16;

    int gbase[6];
    gbase[0] = ks;       gbase[1] = ks + 8;
    gbase[2] = 128 + ks; gbase[3] = 128 + ks + 8;
    gbase[4] = 256 + ks; gbase[5] = 256 + ks + 8;

    unsigned breg[6][6][2];
    #pragma unroll
    for (int kt = 0; kt < 6; kt++)
        #pragma unroll
        for (int nt = 0; nt < 6; nt++) {
            const float* wr = Whh + (ll)(gbase[nt] + m) * HH + kt * 8 + q;
            breg[kt][nt][0] = f2tf32(wr[0]);
            breg[kt][nt][1] = f2tf32(wr[4]);
        }
    #pragma unroll
    for (int kt = 6; kt < 16; kt++)
        #pragma unroll
        for (int nt = 0; nt < 6; nt++) {
            const float* wr = Whh + (ll)(gbase[nt] + m) * HH + kt * 8 + q;
            float* d = sB + (((w * 10 + (kt - 6)) * 6 + nt) * 32 + lane) * 2;
            d[0] = __uint_as_float(f2tf32(wr[0]));
            d[1] = __uint_as_float(f2tf32(wr[4]));
        }

    float bh[3][4];
    #pragma unroll
    for (int g = 0; g < 3; g++)
        #pragma unroll
        for (int p = 0; p < 2; p++) {
            const float2 v = *(const float2*)(bhh + g * 128 + ks + p * 8 + q * 2);
            bh[g][p * 2 + 0] = v.x;
            bh[g][p * 2 + 1] = v.y;
        }

    for (int i = tid; i < 4096; i += 256) hA[i] = 0.f;
    __syncthreads();

    float hold[4];
    #pragma unroll
    for (int p = 0; p < 2; p++) {
        const float2 v = *(const float2*)(hidden + ((ll)dir * BB + b0 + m) * HH + ks + p * 8 + q * 2);
        hold[p * 2 + 0] = v.x;
        hold[p * 2 + 1] = v.y;
        #pragma unroll
        for (int d_ = 0; d_ < 2; d_++) {
            const int k = ks + p * 8 + q * 2 + d_;
            hA[(k >> 3) * 128 + ((m << 2) | (k & 3)) * 4 + ((k & 4) ? 2 : 0)]
                = __uint_as_float(f2tf32(hold[p * 2 + d_]));
        }
    }
    __syncthreads();

    float xv[3][4], xvn[3][4];
    #pragma unroll
    for (int g = 0; g < 3; g++)
        #pragma unroll
        for (int p = 0; p < 2; p++) {
            const float2 v = *(const float2*)(xp + ((ll)(b0 + m)) * G3 + g * 128 + ks + p * 8 + q * 2);
            xv[g][p * 2 + 0] = v.x;
            xv[g][p * 2 + 1] = v.y;
        }

    for (int t = 0; t < TT; t++) {
        const float* hAc = hA + (t & 1) * 2048;
        float* hAn       = hA + ((t + 1) & 1) * 2048;

        const int tn = (t + 1 < TT) ? (t + 1) : t;
        #pragma unroll
        for (int g = 0; g < 3; g++)
            #pragma unroll
            for (int p = 0; p < 2; p++) {
                const float2 v = *(const float2*)(xp + ((ll)tn * BB + b0 + m) * G3 + g * 128 + ks + p * 8 + q * 2);
                xvn[g][p * 2 + 0] = v.x;
                xvn[g][p * 2 + 1] = v.y;
            }

        float acc0[6][4], acc1[6][4];
        #pragma unroll
        for (int nt = 0; nt < 6; nt++)
            #pragma unroll
            for (int c = 0; c < 4; c++) { acc0[nt][c] = 0.f; acc1[nt][c] = 0.f; }

        #pragma unroll
        for (int kt = 0; kt < 16; kt++) {
            uint4 av = *(const uint4*)(hAc + kt * 128 + lane * 4);
            unsigned a[4] = {av.x, av.y, av.z, av.w};
            if (kt < 6) {
                #pragma unroll
                for (int nt = 0; nt < 6; nt++)
                    mma_tf32(acc0[nt], a, breg[kt][nt]);
            } else {
                #pragma unroll
                for (int nt = 0; nt < 6; nt++) {
                    const float2 bv = *(const float2*)(sB + (((w * 10 + (kt - 6)) * 6 + nt) * 32 + lane) * 2);
                    unsigned b[2] = {__float_as_uint(bv.x), __float_as_uint(bv.y)};
                    mma_tf32(acc1[nt], a, b);
                }
            }
        }

        float hnew[4];
        #pragma unroll
        for (int p = 0; p < 2; p++)
            #pragma unroll
            for (int d_ = 0; d_ < 2; d_++) {
                const int i = p * 2 + d_;
                const float hr = acc0[p][d_] + acc1[p][d_];
                const float hz = acc0[2 + p][d_] + acc1[2 + p][d_];
                const float hn = acc0[4 + p][d_] + acc1[4 + p][d_];
                const float rs = xv[0][i] + hr + bh[0][i];
                const float zs = xv[1][i] + hz + bh[1][i];
                const float rg = __fdividef(1.f, 1.f + __expf(-rs));
                const float zg = __fdividef(1.f, 1.f + __expf(-zs));
                const float a_ = xv[2][i] + rg * (hn + bh[2][i]);
                const float e  = __expf(2.f * a_);
                const float n_ = 1.f - __fdividef(2.f, e + 1.f);
                hnew[i] = (1.f - zg) * n_ + zg * hold[i];
                hold[i] = hnew[i];
                const int k = ks + p * 8 + q * 2 + d_;
                hAn[(k >> 3) * 128 + ((m << 2) | (k & 3)) * 4 + ((k & 4) ? 2 : 0)]
                    = __uint_as_float(f2tf32(hnew[i]));
            }

        #pragma unroll
        for (int p = 0; p < 2; p++)
            *(float2*)(ys + ((ll)t * BB + b0 + m) * HH + ks + p * 8 + q * 2)
                = make_float2(hnew[p * 2], hnew[p * 2 + 1]);

        #pragma unroll
        for (int g = 0; g < 3; g++)
            #pragma unroll
            for (int i = 0; i < 4; i++) xv[g][i] = xvn[g][i];

        __syncthreads();
    }
}

// ============================================================
// K3v2: fused hyp GEMM + tanh + hyperbolic scores + rr2.
// One block = 128 rows x full N=256. 512 thr, 16 warps (2m x 8n).
// g_hyp never materialized.
// ============================================================
__global__ __launch_bounds__(512, 1) void k3v2(
    const float* __restrict__ W, const float* __restrict__ bias,
    const float* __restrict__ cent, const float* __restrict__ beta)
{
    extern __shared__ float smf[];
    unsigned* As = (unsigned*)smf;            // 8*ACH
    unsigned* Bs = As + 8 * ACH;              // 8*BCH2
    float* sh2   = smf + K3V2_U32;            // [128][8]
    float* scd   = sh2 + 1024;                // [128][8]
    float* srr   = scd + 1024;                // [128]
    float* scent = srr + 128;                 // [256]
    float* sbias = scent + 256;               // [256]

    const int tid  = threadIdx.x;
    const int lane = tid & 31;
    const int w    = tid >> 5;                // 0..15
    const int wm   = w >> 3;                  // 0..1
    const int wn   = w & 7;                   // 0..7
    const int row0 = blockIdx.x * 128;
    const int t    = row0 >> 9;
    const int b0   = row0 & 511;
    const int tb   = TT - 1 - t;

    if (tid < 256) { scent[tid] = cent[tid]; sbias[tid] = bias[tid]; }
    if (tid < 128) srr[tid] = 0.f;

    float acc[4][4][4];
    #pragma unroll
    for (int i = 0; i < 4; i++)
        #pragma unroll
        for (int j = 0; j < 4; j++)
            #pragma unroll
            for (int q = 0; q < 4; q++) acc[i][j][q] = 0.f;

    const int fl = tid & 15;
    const int rr = tid >> 4;                  // 0..31

    for (int ks = 0; ks < 4; ks++) {
        const int kg4 = ks * 64 + fl * 4;
        __syncthreads();                      // prior slice reads done; srr init visible
        const float* ysrc = (ks < 2) ? (g_ys_f + (ll)t * BB * HH)
                                     : (g_ys_b + (ll)tb * BB * HH);
        const int kk4 = (ks < 2) ? kg4 : (kg4 - HH);
        // stage A (+ raw rr2 partials)
        #pragma unroll
        for (int rp = 0; rp < 4; rp++) {
            const int r = rp * 32 + rr;
            float4 v = *(const float4*)(ysrc + (ll)(b0 + r) * HH + kk4);
            As[a_off(r, fl * 4 + 0)] = f2tf32(v.x);
            As[a_off(r, fl * 4 + 1)] = f2tf32(v.y);
            As[a_off(r, fl * 4 + 2)] = f2tf32(v.z);
            As[a_off(r, fl * 4 + 3)] = f2tf32(v.w);
            float s = v.x * v.x + v.y * v.y + v.z * v.z + v.w * v.w;
            s += __shfl_xor_sync(0xffffffffu, s, 1);
            s += __shfl_xor_sync(0xffffffffu, s, 2);
            s += __shfl_xor_sync(0xffffffffu, s, 4);
            s += __shfl_xor_sync(0xffffffffu, s, 8);
            if (fl == 0) srr[r] += s;         // unique writer per row
        }
        // stage B (256 cols)
        #pragma unroll
        for (int cp = 0; cp < 8; cp++) {
            const int c = cp * 32 + rr;
            float4 v = *(const float4*)(W + (ll)c * DD + kg4);
            Bs[b_off2(c, fl * 4 + 0)] = f2tf32(v.x);
            Bs[b_off2(c, fl * 4 + 1)] = f2tf32(v.y);
            Bs[b_off2(c, fl * 4 + 2)] = f2tf32(v.z);
            Bs[b_off2(c, fl * 4 + 3)] = f2tf32(v.w);
        }
        __syncthreads();
        #pragma unroll
        for (int ck = 0; ck < 8; ck++) {
            unsigned a[4][4], b[4][2];
            #pragma unroll
            for (int i = 0; i < 4; i++) {
                uint4 av = *(const uint4*)(As + ck * ACH + (wm * 4 + i) * 128 + lane * 4);
                a[i][0] = av.x; a[i][1] = av.y; a[i][2] = av.z; a[i][3] = av.w;
            }
            #pragma unroll
            for (int j = 0; j < 4; j++) {
                uint2 bv = *(const uint2*)(Bs + ck * BCH2 + (wn * 4 + j) * 64 + lane * 2);
                b[j][0] = bv.x; b[j][1] = bv.y;
            }
            #pragma unroll
            for (int i = 0; i < 4; i++)
                #pragma unroll
                for (int j = 0; j < 4; j++)
                    mma_tf32(acc[i][j], a[i], b[j]);
        }
    }

    // epilogue: tanh + per-row Sum(hyp^2), Sum(hyp*cent) — all in registers
    float h2p[8], cdp[8];
    #pragma unroll
    for (int i = 0; i < 8; i++) { h2p[i] = 0.f; cdp[i] = 0.f; }

    #pragma unroll
    for (int j = 0; j < 4; j++) {
        const int c0 = wn * 32 + j * 8 + 2 * (lane & 3);
        const float bv0 = sbias[c0], bv1 = sbias[c0 + 1];
        const float cv0 = scent[c0], cv1 = scent[c0 + 1];
        #pragma unroll
        for (int i = 0; i < 4; i++) {
            float v0 = acc[i][j][0] + bv0, v1 = acc[i][j][1] + bv1;
            float v2 = acc[i][j][2] + bv0, v3 = acc[i][j][3] + bv1;
            v0 = 1.f - __fdividef(2.f, __expf(2.f * v0) + 1.f);
            v1 = 1.f - __fdividef(2.f, __expf(2.f * v1) + 1.f);
            v2 = 1.f - __fdividef(2.f, __expf(2.f * v2) + 1.f);
            v3 = 1.f - __fdividef(2.f, __expf(2.f * v3) + 1.f);
            h2p[i * 2]     += v0 * v0 + v1 * v1;
            cdp[i * 2]     += v0 * cv0 + v1 * cv1;
            h2p[i * 2 + 1] += v2 * v2 + v3 * v3;
            cdp[i * 2 + 1] += v2 * cv0 + v3 * cv1;
        }
    }
    // quad reduce (lanes sharing a row differ only in lane&3)
    #pragma unroll
    for (int i = 0; i < 8; i++) {
        h2p[i] += __shfl_xor_sync(0xffffffffu, h2p[i], 1);
        h2p[i] += __shfl_xor_sync(0xffffffffu, h2p[i], 2);
        cdp[i] += __shfl_xor_sync(0xffffffffu, cdp[i], 1);
        cdp[i] += __shfl_xor_sync(0xffffffffu, cdp[i], 2);
    }
    if ((lane & 3) == 0) {
        #pragma unroll
        for (int i = 0; i < 4; i++)
            #pragma unroll
            for (int h = 0; h < 2; h++) {
                const int rloc = wm * 64 + i * 16 + (lane >> 2) + h * 8;
                sh2[rloc * 8 + wn] = h2p[i * 2 + h];
                scd[rloc * 8 + wn] = cdp[i * 2 + h];
            }
    }
    __syncthreads();

    if (tid < 128) {
        const int r = tid;
        float h2 = 0.f, cd = 0.f;
        #pragma unroll
        for (int k = 0; k < 8; k++) { h2 += sh2[r * 8 + k]; cd += scd[r * 8 + k]; }
        const float rh = sqrtf(h2);
        float pm = coshf(rh) * g_cc[0] - (sinhf(rh) / rh) * g_cc[1] * cd;
        pm = fminf(fmaxf(pm, 1.f + EPSF), 1e16f);
        const float dist = logf(pm) + log1pf(sqrtf(pm * pm - 1.f + EPSF) / pm);
        g_scores[row0 + r] = -beta[0] * dist - 1.f;
        g_rr2[row0 + r] = srr[r];
    }
}

// ============================================================
// K5: softmax x gamma Einstein-midpoint pooling + h_output
// ============================================================
__global__ __launch_bounds__(256) void k5_pool(float* __restrict__ out)
{
    __shared__ float wk[128];
    __shared__ float red[128];
    const int b = blockIdx.x, tid = threadIdx.x;

    float s = -1e30f;
    if (tid < 128) {
        s = g_scores[tid * BB + b];
        red[tid] = s;
    }
    __syncthreads();
    for (int o = 64; o; o >>= 1) {
        if (tid < o) red[tid] = fmaxf(red[tid], red[tid + o]);
        __syncthreads();
    }
    const float smax = red[0];
    __syncthreads();

    float myw = 0.f, kf = 0.f;
    if (tid < 128) {
        const float rr = sqrtf(g_rr2[tid * BB + b]);
        const float sh = sinhf(rr), ch = coshf(rr);
        const float th = sh / ch;
        float gsq = 1.f - th * th;
        gsq = fminf(fmaxf(gsq, EPSF), 1.f - EPSF);
        float gam = 1.f / sqrtf(gsq);
        gam = fminf(fmaxf(gam, 1.f + EPSF), 1e16f);
        myw = __expf(s - smax) * gam;
        kf = th / rr;
        red[tid] = myw;
    }
    __syncthreads();
    for (int o = 64; o; o >>= 1) {
        if (tid < o) red[tid] += red[tid + o];
        __syncthreads();
    }
    const float wsum = red[0];
    if (tid < 128) wk[tid] = (myw / wsum) * kf;
    __syncthreads();

    float acc = 0.f;
    if (tid < 128) {
        for (int t = 0; t < TT; t++)
            acc += wk[t] * g_ys_f[((ll)t * BB + b) * HH + tid];
    } else {
        const int k = tid - 128;
        for (int t = 0; t < TT; t++)
            acc += wk[t] * g_ys_b[((ll)(TT - 1 - t) * BB + b) * HH + k];
    }
    out[b * DD + tid] = acc;

    float* hout = out + BB * DD;
    if (tid < 128) {
        hout[b * HH + tid] = g_ys_f[((ll)(TT - 1) * BB + b) * HH + tid];
    } else {
        const int k = tid - 128;
        hout[BB * HH + b * HH + k] = g_ys_b[((ll)(TT - 1) * BB + b) * HH + k];
    }
}

// ============================================================
extern "C" void kernel_launch(void* const* d_in, const int* in_sizes, int n_in,
                              void* d_out, int out_size)
{
    const int*   tokens = (const int*)d_in[0];
    const float* hidden = (const float*)d_in[1];
    const float* emb    = (const float*)d_in[2];
    const float* W_ih_f = (const float*)d_in[3];
    const float* W_hh_f = (const float*)d_in[4];
    const float* b_ih_f = (const float*)d_in[5];
    const float* b_hh_f = (const float*)d_in[6];
    const float* W_ih_b = (const float*)d_in[7];
    const float* W_hh_b = (const float*)d_in[8];
    const float* b_ih_b = (const float*)d_in[9];
    const float* b_hh_b = (const float*)d_in[10];
    const float* attn2W = (const float*)d_in[11];
    const float* attn2b = (const float*)d_in[12];
    const float* cent   = (const float*)d_in[13];
    const float* beta   = (const float*)d_in[14];
    float* out = (float*)d_out;

    cudaFuncSetAttribute(k1_mma, cudaFuncAttributeMaxDynamicSharedMemorySize, K1_SMEM);
    cudaFuncSetAttribute(k2_mma, cudaFuncAttributeMaxDynamicSharedMemorySize, K2_SMEM);
    cudaFuncSetAttribute(k3v2,   cudaFuncAttributeMaxDynamicSharedMemorySize, K3V2_SMEM);

    // launch #4 = k3v2 (ncu capture slot)
    k0_cent<<<1, 32>>>(cent);
    k1_mma<<<dim3(6, 512), 256, K1_SMEM>>>(tokens, emb, W_ih_f, b_ih_f, W_ih_b, b_ih_b);
    k2_mma<<<128, 256, K2_SMEM>>>(hidden, W_hh_f, b_hh_f, W_hh_b, b_hh_b);
    k3v2<<<512, 512, K3V2_SMEM>>>(attn2W, attn2b, cent, beta);
    k5_pool<<<512, 256>>>(out);
}